// round 5
// baseline (speedup 1.0000x reference)
#include <cuda_runtime.h>
#include <cuda_bf16.h>
#include <cstdint>

#define N_PTS 200000
#define CDIM 96
#define FDIM 96
#define NCOLS 3
#define HDIM 288          // NCOLS * FDIM
#define EPSV 1e-3f

// ---------------- scratch (device globals: no allocation allowed) ----------
__device__ float g_Z [(size_t)N_PTS * HDIM];   // stage-1 GEMM out
__device__ float g_Zh[(size_t)N_PTS * HDIM];   // stage-2 GEMM out
__device__ int   g_prev[NCOLS * N_PTS];
__device__ int   g_next[NCOLS * N_PTS];
// A operands pre-split to bf16 hi/lo
__device__ __nv_bfloat16 g_Xh[(size_t)N_PTS * CDIM];
__device__ __nv_bfloat16 g_Xl[(size_t)N_PTS * CDIM];
__device__ __nv_bfloat16 g_hh[(size_t)N_PTS * HDIM];
__device__ __nv_bfloat16 g_hl[(size_t)N_PTS * HDIM];
// bf16-split weights, MMA layout: B[n][k]  (n = tap*FDIM + f, k = input chan)
__device__ __nv_bfloat16 g_B1h[HDIM * CDIM];
__device__ __nv_bfloat16 g_B1l[HDIM * CDIM];
__device__ __nv_bfloat16 g_B2h[HDIM * HDIM];
__device__ __nv_bfloat16 g_B2l[HDIM * HDIM];

// ======================= helpers ==========================================
__device__ __forceinline__ uint32_t smem_u32(const void* p) {
    uint32_t a;
    asm("{ .reg .u64 t; cvta.to.shared.u64 t, %1; cvt.u32.u64 %0, t; }"
        : "=r"(a) : "l"(p));
    return a;
}
__device__ __forceinline__ void cp16(uint32_t dst, const void* src) {
    asm volatile("cp.async.ca.shared.global [%0], [%1], 16;"
                 :: "r"(dst), "l"(src) : "memory");
}
__device__ __forceinline__ void cp16p(uint32_t dst, const void* src, uint32_t sz) {
    asm volatile("cp.async.ca.shared.global [%0], [%1], 16, %2;"
                 :: "r"(dst), "l"(src), "r"(sz) : "memory");
}
#define CP_COMMIT() asm volatile("cp.async.commit_group;" ::: "memory")

// D += A*B  (m16n8k16, bf16 in, fp32 acc)
__device__ __forceinline__ void mma_bf16(float* d, const uint32_t* a,
                                         const uint32_t* b) {
    asm volatile(
        "mma.sync.aligned.m16n8k16.row.col.f32.bf16.bf16.f32 "
        "{%0,%1,%2,%3}, {%4,%5,%6,%7}, {%8,%9}, {%0,%1,%2,%3};"
        : "+f"(d[0]), "+f"(d[1]), "+f"(d[2]), "+f"(d[3])
        : "r"(a[0]), "r"(a[1]), "r"(a[2]), "r"(a[3]), "r"(b[0]), "r"(b[1]));
}

// fp32 pair -> bf16x2 hi + bf16x2 lo (residual)
__device__ __forceinline__ void split2(float2 v, uint32_t& hi, uint32_t& lo) {
    uint32_t h;
    asm("cvt.rn.bf16x2.f32 %0, %1, %2;" : "=r"(h) : "f"(v.y), "f"(v.x));
    float hx = __uint_as_float(h << 16);
    float hy = __uint_as_float(h & 0xFFFF0000u);
    float rx = v.x - hx, ry = v.y - hy;
    uint32_t l;
    asm("cvt.rn.bf16x2.f32 %0, %1, %2;" : "=r"(l) : "f"(ry), "f"(rx));
    hi = h; lo = l;
}
// bf16x2 word -> float2 (exact)
__device__ __forceinline__ float2 up2(uint32_t u) {
    return make_float2(__uint_as_float(u << 16),
                       __uint_as_float(u & 0xFFFF0000u));
}

// ---------------- split X into bf16 hi/lo ----------------------------------
__global__ void split_x_kernel(const float* __restrict__ X) {
    int idx = blockIdx.x * 256 + threadIdx.x;        // groups of 4 floats
    if (idx >= N_PTS * (CDIM / 4)) return;
    float4 v = ((const float4*)X)[idx];
    uint32_t h0, l0, h1, l1;
    split2(make_float2(v.x, v.y), h0, l0);
    split2(make_float2(v.z, v.w), h1, l1);
    ((uint2*)g_Xh)[idx] = make_uint2(h0, h1);
    ((uint2*)g_Xl)[idx] = make_uint2(l0, l1);
}

// ---------------- pack weights: bf16 hi/lo split, [n][k] MMA layout --------
__global__ void pack_w_kernel(const float* __restrict__ W1,
                              const float* __restrict__ W2) {
    int t = blockIdx.x * blockDim.x + threadIdx.x;
    if (t < HDIM * HDIM) {                       // W2: (3, 288, 96)
        int n = t / HDIM, k = t % HDIM;
        int tap = n / FDIM, f = n % FDIM;
        float w = W2[((size_t)tap * HDIM + k) * FDIM + f];
        __nv_bfloat16 hi = __float2bfloat16_rn(w);
        g_B2h[(size_t)n * HDIM + k] = hi;
        g_B2l[(size_t)n * HDIM + k] = __float2bfloat16_rn(w - __bfloat162float(hi));
    }
    if (t < HDIM * CDIM) {                       // W1: (3, 96, 96)
        int n = t / CDIM, k = t % CDIM;
        int tap = n / FDIM, f = n % FDIM;
        float w = W1[((size_t)tap * CDIM + k) * FDIM + f];
        __nv_bfloat16 hi = __float2bfloat16_rn(w);
        g_B1h[(size_t)n * CDIM + k] = hi;
        g_B1l[(size_t)n * CDIM + k] = __float2bfloat16_rn(w - __bfloat162float(hi));
    }
}

// ---------------- neighbor maps --------------------------------------------
__global__ void prevnext_kernel(const int* __restrict__ index) {
    int t = blockIdx.x * blockDim.x + threadIdx.x;
    if (t >= NCOLS * N_PTS) return;
    int i = t / NCOLS;
    int c = t % NCOLS;
    int p = index[t];
    g_prev[c * N_PTS + p] = (i > 0)         ? index[t - NCOLS] : -1;
    g_next[c * N_PTS + p] = (i < N_PTS - 1) ? index[t + NCOLS] : -1;
}

// ============== split-bf16 HMMA GEMM:  C[M,288] = A[M,K] @ B[288,K]^T ======
// CTA: BM=128, BN=96, BK=32. 8 warps 4(M) x 2(N); warp tile 32x48 (48 acc).
// A pre-split bf16 hi/lo in gmem. 3-stage cp.async pipeline.
// smem per buf: Ah 128x80B, Al 128x80B, Bh 96x80B, Bl 96x80B = 35840 B.
#define BUF_SZ   35840
#define AL_OFF   10240
#define BH_OFF   20480
#define BL_OFF   28160
#define GSM_TOTAL (3 * BUF_SZ)       // 107520

template <int KDIM>
__device__ __forceinline__ void gemm_stage(
        int tid, int row0, int col0, int k0, int buf,
        const __nv_bfloat16* __restrict__ Ahp,
        const __nv_bfloat16* __restrict__ Alp,
        const __nv_bfloat16* __restrict__ Bhp,
        const __nv_bfloat16* __restrict__ Blp,
        uint32_t sb) {
    uint32_t base = sb + buf * BUF_SZ;
    // A: 128 rows x 32 k bf16 = 512 x 16B per array; 2 per thread per array
    #pragma unroll
    for (int i = 0; i < 2; i++) {
        int cid = tid + i * 256;
        int r = cid >> 2, c = cid & 3;
        int gr = row0 + r;
        uint32_t sz = (gr < N_PTS) ? 16u : 0u;
        size_t go = (size_t)gr * KDIM + k0 + c * 8;
        uint32_t so = (uint32_t)(r * 80 + c * 16);
        cp16p(base + so,          Ahp + go, sz);
        cp16p(base + AL_OFF + so, Alp + go, sz);
    }
    // B: 96 rows x 32 k = 384 x 16B per array
    for (int idx = tid; idx < 384; idx += 256) {
        int r = idx >> 2, c = idx & 3;
        size_t go = (size_t)(col0 + r) * KDIM + k0 + c * 8;
        uint32_t so = (uint32_t)(r * 80 + c * 16);
        cp16(base + BH_OFF + so, Bhp + go);
        cp16(base + BL_OFF + so, Blp + go);
    }
}

template <int STAGE>
__global__ __launch_bounds__(256, 2)
void mma_gemm_kernel() {
    constexpr int KDIM = (STAGE == 1) ? CDIM : HDIM;
    constexpr int NCH  = KDIM / 32;
    const __nv_bfloat16* __restrict__ Ahp = (STAGE == 1) ? g_Xh : g_hh;
    const __nv_bfloat16* __restrict__ Alp = (STAGE == 1) ? g_Xl : g_hl;
    const __nv_bfloat16* __restrict__ Bhp = (STAGE == 1) ? g_B1h : g_B2h;
    const __nv_bfloat16* __restrict__ Blp = (STAGE == 1) ? g_B1l : g_B2l;
    float* __restrict__ C = (STAGE == 1) ? g_Z : g_Zh;

    extern __shared__ char smem[];
    const uint32_t sb = smem_u32(smem);

    const int tid  = threadIdx.x;
    const int wid  = tid >> 5;
    const int lane = tid & 31;
    const int g    = lane >> 2;        // 0..7
    const int tg   = lane & 3;         // 0..3
    const int wm   = wid & 3;          // M warp 0..3
    const int wn   = wid >> 2;         // N warp 0..1
    const int row0 = blockIdx.x * 128;
    const int col0 = blockIdx.y * 96;

    float acc[2][6][4];
    #pragma unroll
    for (int mf = 0; mf < 2; mf++)
        #pragma unroll
        for (int nf = 0; nf < 6; nf++)
            #pragma unroll
            for (int i = 0; i < 4; i++) acc[mf][nf][i] = 0.f;

    gemm_stage<KDIM>(tid, row0, col0, 0, 0, Ahp, Alp, Bhp, Blp, sb);
    CP_COMMIT();
    gemm_stage<KDIM>(tid, row0, col0, 32, 1, Ahp, Alp, Bhp, Blp, sb);
    CP_COMMIT();

    for (int kc = 0; kc < NCH; kc++) {
        if (kc + 2 < NCH) {
            gemm_stage<KDIM>(tid, row0, col0, (kc + 2) * 32, (kc + 2) % 3,
                             Ahp, Alp, Bhp, Blp, sb);
            CP_COMMIT();
            asm volatile("cp.async.wait_group 2;" ::: "memory");
        } else if (kc + 1 < NCH) {
            asm volatile("cp.async.wait_group 1;" ::: "memory");
        } else {
            asm volatile("cp.async.wait_group 0;" ::: "memory");
        }
        __syncthreads();

        const char* base = smem + (kc % 3) * BUF_SZ;

        #pragma unroll
        for (int ks = 0; ks < 2; ks++) {
            const int kk = ks * 16 + 2 * tg;      // bf16 element offset in row
            uint32_t AH[2][4], AL[2][4];
            #pragma unroll
            for (int mf = 0; mf < 2; mf++) {
                int r = wm * 32 + mf * 16 + g;
                const char* ah = base + r * 80 + kk * 2;
                const char* al = ah + AL_OFF;
                AH[mf][0] = *(const uint32_t*)(ah);
                AH[mf][1] = *(const uint32_t*)(ah + 8 * 80);
                AH[mf][2] = *(const uint32_t*)(ah + 16);
                AH[mf][3] = *(const uint32_t*)(ah + 8 * 80 + 16);
                AL[mf][0] = *(const uint32_t*)(al);
                AL[mf][1] = *(const uint32_t*)(al + 8 * 80);
                AL[mf][2] = *(const uint32_t*)(al + 16);
                AL[mf][3] = *(const uint32_t*)(al + 8 * 80 + 16);
            }
            #pragma unroll
            for (int nf = 0; nf < 6; nf++) {
                int n = wn * 48 + nf * 8 + g;
                const char* bp = base + BH_OFF + n * 80 + kk * 2;
                uint32_t bh[2] = { *(const uint32_t*)bp,
                                   *(const uint32_t*)(bp + 16) };
                uint32_t bl[2] = { *(const uint32_t*)(bp + (BL_OFF - BH_OFF)),
                                   *(const uint32_t*)(bp + (BL_OFF - BH_OFF) + 16) };
                #pragma unroll
                for (int mf = 0; mf < 2; mf++) {
                    mma_bf16(acc[mf][nf], AH[mf], bh);
                    mma_bf16(acc[mf][nf], AH[mf], bl);
                    mma_bf16(acc[mf][nf], AL[mf], bh);
                }
            }
        }
        __syncthreads();
    }

    // epilogue: fp32 accumulators -> C
    #pragma unroll
    for (int mf = 0; mf < 2; mf++) {
        int row = row0 + wm * 32 + mf * 16 + g;
        #pragma unroll
        for (int nf = 0; nf < 6; nf++) {
            int col = col0 + wn * 48 + nf * 8 + 2 * tg;
            if (row < N_PTS)
                *(float2*)(C + (size_t)row * HDIM + col) =
                    make_float2(acc[mf][nf][0], acc[mf][nf][1]);
            if (row + 8 < N_PTS)
                *(float2*)(C + (size_t)(row + 8) * HDIM + col) =
                    make_float2(acc[mf][nf][2], acc[mf][nf][3]);
        }
    }
}

// -------- assemble stage 1:  h = relu(b1 + 3 gathered taps) -> bf16 hi/lo --
__global__ __launch_bounds__(256)
void assemble1_kernel(const float* __restrict__ b1) {
    int idx = blockIdx.x * 256 + threadIdx.x;      // N_PTS * 72 float4 tasks
    if (idx >= N_PTS * 72) return;
    int p = idx / 72;
    int gidx = idx - p * 72;
    int c = gidx / 24;          // tap 0..2
    int j = gidx - c * 24;      // float4 within 96
    int prev = g_prev[c * N_PTS + p];
    int next = g_next[c * N_PTS + p];
    float4 v = ((const float4*)b1)[j];
    if (prev >= 0) {
        float4 z = *(const float4*)(g_Z + (size_t)prev * HDIM + j * 4);
        v.x += z.x; v.y += z.y; v.z += z.z; v.w += z.w;
    }
    {
        float4 z = *(const float4*)(g_Z + (size_t)p * HDIM + FDIM + j * 4);
        v.x += z.x; v.y += z.y; v.z += z.z; v.w += z.w;
    }
    if (next >= 0) {
        float4 z = *(const float4*)(g_Z + (size_t)next * HDIM + 2 * FDIM + j * 4);
        v.x += z.x; v.y += z.y; v.z += z.z; v.w += z.w;
    }
    v.x = fmaxf(v.x, 0.f); v.y = fmaxf(v.y, 0.f);
    v.z = fmaxf(v.z, 0.f); v.w = fmaxf(v.w, 0.f);
    uint32_t h0, l0, h1, l1;
    split2(make_float2(v.x, v.y), h0, l0);
    split2(make_float2(v.z, v.w), h1, l1);
    int o = p * 72 + c * 24 + j;                   // uint2 (4-elem) index
    ((uint2*)g_hh)[o] = make_uint2(h0, h1);
    ((uint2*)g_hl)[o] = make_uint2(l0, l1);
}

// ------- assemble stage 2 + residual + layernorm (warp per point) ----------
__global__ __launch_bounds__(256)
void assemble2_ln_kernel(const float* __restrict__ b2,
                         const float* __restrict__ gamma,
                         const float* __restrict__ beta,
                         float* __restrict__ out) {
    int p    = (blockIdx.x * 256 + threadIdx.x) >> 5;   // warp per point
    int lane = threadIdx.x & 31;
    float4 xv[3];
    float s = 0.f, q = 0.f;
    if (lane < 24) {
        #pragma unroll
        for (int c = 0; c < 3; c++) {
            int prev = g_prev[c * N_PTS + p];
            int next = g_next[c * N_PTS + p];
            float4 v = ((const float4*)b2)[lane];
            if (prev >= 0) {
                float4 z = *(const float4*)(g_Zh + (size_t)prev * HDIM + lane * 4);
                v.x += z.x; v.y += z.y; v.z += z.z; v.w += z.w;
            }
            {
                float4 z = *(const float4*)(g_Zh + (size_t)p * HDIM + FDIM + lane * 4);
                v.x += z.x; v.y += z.y; v.z += z.z; v.w += z.w;
            }
            if (next >= 0) {
                float4 z = *(const float4*)(g_Zh + (size_t)next * HDIM + 2 * FDIM + lane * 4);
                v.x += z.x; v.y += z.y; v.z += z.z; v.w += z.w;
            }
            int o = p * 72 + c * 24 + lane;
            uint2 hh = ((const uint2*)g_hh)[o];
            uint2 hl = ((const uint2*)g_hl)[o];
            float2 a0 = up2(hh.x), a1 = up2(hh.y);
            float2 b0 = up2(hl.x), b1 = up2(hl.y);
            float4 x;
            x.x = (a0.x + b0.x) + fmaxf(v.x, 0.f);
            x.y = (a0.y + b0.y) + fmaxf(v.y, 0.f);
            x.z = (a1.x + b1.x) + fmaxf(v.z, 0.f);
            x.w = (a1.y + b1.y) + fmaxf(v.w, 0.f);
            xv[c] = x;
            s += x.x + x.y + x.z + x.w;
            q += x.x * x.x + x.y * x.y + x.z * x.z + x.w * x.w;
        }
    }
    #pragma unroll
    for (int o = 16; o > 0; o >>= 1) {
        s += __shfl_xor_sync(0xffffffffu, s, o);
        q += __shfl_xor_sync(0xffffffffu, q, o);
    }
    float mu  = s * (1.f / HDIM);
    float var = q * (1.f / HDIM) - mu * mu;
    float r   = rsqrtf(var + EPSV);
    if (lane < 24) {
        #pragma unroll
        for (int c = 0; c < 3; c++) {
            float4 gm = ((const float4*)gamma)[c * 24 + lane];
            float4 bt = ((const float4*)beta)[c * 24 + lane];
            float4 x  = xv[c];
            float4 o4;
            o4.x = (x.x - mu) * r * gm.x + bt.x;
            o4.y = (x.y - mu) * r * gm.y + bt.y;
            o4.z = (x.z - mu) * r * gm.z + bt.z;
            o4.w = (x.w - mu) * r * gm.w + bt.w;
            *(float4*)(out + (size_t)p * HDIM + c * FDIM + lane * 4) = o4;
        }
    }
}

// ---------------- index pass-through tail ----------------------------------
__global__ void copy_index_kernel(const int* __restrict__ index,
                                  float* __restrict__ out, int count) {
    int t = blockIdx.x * blockDim.x + threadIdx.x;
    if (t < count) out[t] = (float)index[t];
}

// ---------------------------------------------------------------------------
extern "C" void kernel_launch(void* const* d_in, const int* in_sizes, int n_in,
                              void* d_out, int out_size) {
    const float* X     = (const float*)d_in[0];
    const int*   index = (const int*)  d_in[1];
    const float* W1    = (const float*)d_in[2];
    const float* b1    = (const float*)d_in[3];
    const float* W2    = (const float*)d_in[4];
    const float* b2    = (const float*)d_in[5];
    const float* gamma = (const float*)d_in[6];
    const float* beta  = (const float*)d_in[7];
    float* out = (float*)d_out;

    cudaFuncSetAttribute(mma_gemm_kernel<1>,
                         cudaFuncAttributeMaxDynamicSharedMemorySize, GSM_TOTAL);
    cudaFuncSetAttribute(mma_gemm_kernel<2>,
                         cudaFuncAttributeMaxDynamicSharedMemorySize, GSM_TOTAL);

    split_x_kernel<<<(N_PTS * 24 + 255) / 256, 256>>>(X);
    pack_w_kernel<<<(HDIM * HDIM + 255) / 256, 256>>>(W1, W2);
    prevnext_kernel<<<(NCOLS * N_PTS + 255) / 256, 256>>>(index);

    dim3 gg((N_PTS + 127) / 128, 3);
    mma_gemm_kernel<1><<<gg, 256, GSM_TOTAL>>>();        // Z  = X @ B1^T
    assemble1_kernel<<<(N_PTS * 72 + 255) / 256, 256>>>(b1);
    mma_gemm_kernel<2><<<gg, 256, GSM_TOTAL>>>();        // Zh = h @ B2^T
    assemble2_ln_kernel<<<(N_PTS * 32 + 255) / 256, 256>>>(b2, gamma, beta, out);

    int tail = out_size - N_PTS * HDIM;
    if (tail > 0) {
        if (tail > NCOLS * N_PTS) tail = NCOLS * N_PTS;
        copy_index_kernel<<<(tail + 255) / 256, 256>>>(
            index, out + (size_t)N_PTS * HDIM, tail);
    }
}

// round 6
// speedup vs baseline: 1.2817x; 1.2817x over previous
#include <cuda_runtime.h>
#include <cuda_bf16.h>
#include <cstdint>

#define N_PTS 200000
#define CDIM 96
#define FDIM 96
#define NCOLS 3
#define HDIM 288          // NCOLS * FDIM
#define EPSV 1e-3f

// ---------------- scratch (device globals: no allocation allowed) ----------
__device__ float g_Z [(size_t)N_PTS * HDIM];   // stage-1 GEMM out
__device__ float g_Zh[(size_t)N_PTS * HDIM];   // stage-2 GEMM out
__device__ int   g_prev[NCOLS * N_PTS];
__device__ int   g_next[NCOLS * N_PTS];
// A operands pre-split to bf16 hi/lo
__device__ __nv_bfloat16 g_Xh[(size_t)N_PTS * CDIM];
__device__ __nv_bfloat16 g_Xl[(size_t)N_PTS * CDIM];
__device__ __nv_bfloat16 g_hh[(size_t)N_PTS * HDIM];
__device__ __nv_bfloat16 g_hl[(size_t)N_PTS * HDIM];
// bf16-split weights, MMA layout: B[n][k]  (n = tap*FDIM + f, k = input chan)
__device__ __nv_bfloat16 g_B1h[HDIM * CDIM];
__device__ __nv_bfloat16 g_B1l[HDIM * CDIM];
__device__ __nv_bfloat16 g_B2h[HDIM * HDIM];
__device__ __nv_bfloat16 g_B2l[HDIM * HDIM];

// ======================= helpers ==========================================
__device__ __forceinline__ uint32_t smem_u32(const void* p) {
    uint32_t a;
    asm("{ .reg .u64 t; cvta.to.shared.u64 t, %1; cvt.u32.u64 %0, t; }"
        : "=r"(a) : "l"(p));
    return a;
}
__device__ __forceinline__ void cp16(uint32_t dst, const void* src) {
    asm volatile("cp.async.ca.shared.global [%0], [%1], 16;"
                 :: "r"(dst), "l"(src) : "memory");
}
__device__ __forceinline__ void cp16p(uint32_t dst, const void* src, uint32_t sz) {
    asm volatile("cp.async.ca.shared.global [%0], [%1], 16, %2;"
                 :: "r"(dst), "l"(src), "r"(sz) : "memory");
}
#define CP_COMMIT() asm volatile("cp.async.commit_group;" ::: "memory")

// D += A*B  (m16n8k16, bf16 in, fp32 acc)
__device__ __forceinline__ void mma_bf16(float* d, const uint32_t* a,
                                         const uint32_t* b) {
    asm volatile(
        "mma.sync.aligned.m16n8k16.row.col.f32.bf16.bf16.f32 "
        "{%0,%1,%2,%3}, {%4,%5,%6,%7}, {%8,%9}, {%0,%1,%2,%3};"
        : "+f"(d[0]), "+f"(d[1]), "+f"(d[2]), "+f"(d[3])
        : "r"(a[0]), "r"(a[1]), "r"(a[2]), "r"(a[3]), "r"(b[0]), "r"(b[1]));
}

// fp32 pair -> bf16x2 hi + bf16x2 lo (residual)
__device__ __forceinline__ void split2(float2 v, uint32_t& hi, uint32_t& lo) {
    uint32_t h;
    asm("cvt.rn.bf16x2.f32 %0, %1, %2;" : "=r"(h) : "f"(v.y), "f"(v.x));
    float hx = __uint_as_float(h << 16);
    float hy = __uint_as_float(h & 0xFFFF0000u);
    float rx = v.x - hx, ry = v.y - hy;
    uint32_t l;
    asm("cvt.rn.bf16x2.f32 %0, %1, %2;" : "=r"(l) : "f"(ry), "f"(rx));
    hi = h; lo = l;
}
// bf16x2 word -> float2 (exact)
__device__ __forceinline__ float2 up2(uint32_t u) {
    return make_float2(__uint_as_float(u << 16),
                       __uint_as_float(u & 0xFFFF0000u));
}

// ---------------- split X into bf16 hi/lo ----------------------------------
__global__ void split_x_kernel(const float* __restrict__ X) {
    int idx = blockIdx.x * 256 + threadIdx.x;        // groups of 4 floats
    if (idx >= N_PTS * (CDIM / 4)) return;
    float4 v = ((const float4*)X)[idx];
    uint32_t h0, l0, h1, l1;
    split2(make_float2(v.x, v.y), h0, l0);
    split2(make_float2(v.z, v.w), h1, l1);
    ((uint2*)g_Xh)[idx] = make_uint2(h0, h1);
    ((uint2*)g_Xl)[idx] = make_uint2(l0, l1);
}

// ---------------- pack weights: bf16 hi/lo split, [n][k] MMA layout --------
__global__ void pack_w_kernel(const float* __restrict__ W1,
                              const float* __restrict__ W2) {
    int t = blockIdx.x * blockDim.x + threadIdx.x;
    if (t < HDIM * HDIM) {                       // W2: (3, 288, 96)
        int n = t / HDIM, k = t % HDIM;
        int tap = n / FDIM, f = n % FDIM;
        float w = W2[((size_t)tap * HDIM + k) * FDIM + f];
        __nv_bfloat16 hi = __float2bfloat16_rn(w);
        g_B2h[(size_t)n * HDIM + k] = hi;
        g_B2l[(size_t)n * HDIM + k] = __float2bfloat16_rn(w - __bfloat162float(hi));
    }
    if (t < HDIM * CDIM) {                       // W1: (3, 96, 96)
        int n = t / CDIM, k = t % CDIM;
        int tap = n / FDIM, f = n % FDIM;
        float w = W1[((size_t)tap * CDIM + k) * FDIM + f];
        __nv_bfloat16 hi = __float2bfloat16_rn(w);
        g_B1h[(size_t)n * CDIM + k] = hi;
        g_B1l[(size_t)n * CDIM + k] = __float2bfloat16_rn(w - __bfloat162float(hi));
    }
}

// ---------------- neighbor maps --------------------------------------------
__global__ void prevnext_kernel(const int* __restrict__ index) {
    int t = blockIdx.x * blockDim.x + threadIdx.x;
    if (t >= NCOLS * N_PTS) return;
    int i = t / NCOLS;
    int c = t % NCOLS;
    int p = index[t];
    g_prev[c * N_PTS + p] = (i > 0)         ? index[t - NCOLS] : -1;
    g_next[c * N_PTS + p] = (i < N_PTS - 1) ? index[t + NCOLS] : -1;
}

// ============== split-bf16 HMMA GEMM:  C[M,288] = A[M,K] @ B[288,K]^T ======
// CTA: BM=128, BN=96, BK=32. 8 warps 4(M) x 2(N); warp tile 32x48 (48 acc).
// A pre-split bf16 hi/lo in gmem. 2-stage cp.async pipeline -> 2 CTAs/SM.
// smem per buf: Ah 128x80B, Al 128x80B, Bh 96x80B, Bl 96x80B = 35840 B.
#define BUF_SZ   35840
#define AL_OFF   10240
#define BH_OFF   20480
#define BL_OFF   28160
#define GSM_TOTAL (2 * BUF_SZ)       // 71680 -> 2 CTAs/SM fits
#define N_MTILE  1563                // ceil(200000/128)

template <int KDIM>
__device__ __forceinline__ void gemm_stage(
        int tid, int row0, int col0, int k0, int buf,
        const __nv_bfloat16* __restrict__ Ahp,
        const __nv_bfloat16* __restrict__ Alp,
        const __nv_bfloat16* __restrict__ Bhp,
        const __nv_bfloat16* __restrict__ Blp,
        uint32_t sb) {
    uint32_t base = sb + buf * BUF_SZ;
    // A: 128 rows x 32 k bf16 = 512 x 16B per array; 2 per thread per array
    #pragma unroll
    for (int i = 0; i < 2; i++) {
        int cid = tid + i * 256;
        int r = cid >> 2, c = cid & 3;
        int gr = row0 + r;
        uint32_t sz = (gr < N_PTS) ? 16u : 0u;
        size_t go = (size_t)gr * KDIM + k0 + c * 8;
        uint32_t so = (uint32_t)(r * 80 + c * 16);
        cp16p(base + so,          Ahp + go, sz);
        cp16p(base + AL_OFF + so, Alp + go, sz);
    }
    // B: 96 rows x 32 k = 384 x 16B per array
    for (int idx = tid; idx < 384; idx += 256) {
        int r = idx >> 2, c = idx & 3;
        size_t go = (size_t)(col0 + r) * KDIM + k0 + c * 8;
        uint32_t so = (uint32_t)(r * 80 + c * 16);
        cp16(base + BH_OFF + so, Bhp + go);
        cp16(base + BL_OFF + so, Blp + go);
    }
}

template <int STAGE>
__global__ __launch_bounds__(256, 2)
void mma_gemm_kernel() {
    constexpr int KDIM = (STAGE == 1) ? CDIM : HDIM;
    constexpr int NCH  = KDIM / 32;
    const __nv_bfloat16* __restrict__ Ahp = (STAGE == 1) ? g_Xh : g_hh;
    const __nv_bfloat16* __restrict__ Alp = (STAGE == 1) ? g_Xl : g_hl;
    const __nv_bfloat16* __restrict__ Bhp = (STAGE == 1) ? g_B1h : g_B2h;
    const __nv_bfloat16* __restrict__ Blp = (STAGE == 1) ? g_B1l : g_B2l;
    float* __restrict__ C = (STAGE == 1) ? g_Z : g_Zh;

    extern __shared__ char smem[];
    const uint32_t sb = smem_u32(smem);

    const int tid  = threadIdx.x;
    const int wid  = tid >> 5;
    const int lane = tid & 31;
    const int g    = lane >> 2;        // 0..7
    const int tg   = lane & 3;         // 0..3
    const int wm   = wid & 3;          // M warp 0..3
    const int wn   = wid >> 2;         // N warp 0..1
    const int row0 = blockIdx.x * 128;
    const int col0 = blockIdx.y * 96;

    float acc[2][6][4];
    #pragma unroll
    for (int mf = 0; mf < 2; mf++)
        #pragma unroll
        for (int nf = 0; nf < 6; nf++)
            #pragma unroll
            for (int i = 0; i < 4; i++) acc[mf][nf][i] = 0.f;

    gemm_stage<KDIM>(tid, row0, col0, 0, 0, Ahp, Alp, Bhp, Blp, sb);
    CP_COMMIT();

    for (int kc = 0; kc < NCH; kc++) {
        if (kc + 1 < NCH) {
            gemm_stage<KDIM>(tid, row0, col0, (kc + 1) * 32, (kc + 1) & 1,
                             Ahp, Alp, Bhp, Blp, sb);
            CP_COMMIT();
            asm volatile("cp.async.wait_group 1;" ::: "memory");
        } else {
            asm volatile("cp.async.wait_group 0;" ::: "memory");
        }
        __syncthreads();

        const char* base = smem + (kc & 1) * BUF_SZ;

        #pragma unroll
        for (int ks = 0; ks < 2; ks++) {
            const int kk = ks * 16 + 2 * tg;      // bf16 element offset in row
            uint32_t AH[2][4], AL[2][4];
            #pragma unroll
            for (int mf = 0; mf < 2; mf++) {
                int r = wm * 32 + mf * 16 + g;
                const char* ah = base + r * 80 + kk * 2;
                const char* al = ah + AL_OFF;
                AH[mf][0] = *(const uint32_t*)(ah);
                AH[mf][1] = *(const uint32_t*)(ah + 8 * 80);
                AH[mf][2] = *(const uint32_t*)(ah + 16);
                AH[mf][3] = *(const uint32_t*)(ah + 8 * 80 + 16);
                AL[mf][0] = *(const uint32_t*)(al);
                AL[mf][1] = *(const uint32_t*)(al + 8 * 80);
                AL[mf][2] = *(const uint32_t*)(al + 16);
                AL[mf][3] = *(const uint32_t*)(al + 8 * 80 + 16);
            }
            #pragma unroll
            for (int nf = 0; nf < 6; nf++) {
                int n = wn * 48 + nf * 8 + g;
                const char* bp = base + BH_OFF + n * 80 + kk * 2;
                uint32_t bh[2] = { *(const uint32_t*)bp,
                                   *(const uint32_t*)(bp + 16) };
                uint32_t bl[2] = { *(const uint32_t*)(bp + (BL_OFF - BH_OFF)),
                                   *(const uint32_t*)(bp + (BL_OFF - BH_OFF) + 16) };
                #pragma unroll
                for (int mf = 0; mf < 2; mf++) {
                    mma_bf16(acc[mf][nf], AH[mf], bh);
                    mma_bf16(acc[mf][nf], AH[mf], bl);
                    mma_bf16(acc[mf][nf], AL[mf], bh);
                }
            }
        }
        __syncthreads();
    }

    // epilogue: fp32 accumulators -> C
    #pragma unroll
    for (int mf = 0; mf < 2; mf++) {
        int row = row0 + wm * 32 + mf * 16 + g;
        #pragma unroll
        for (int nf = 0; nf < 6; nf++) {
            int col = col0 + wn * 48 + nf * 8 + 2 * tg;
            if (row < N_PTS)
                *(float2*)(C + (size_t)row * HDIM + col) =
                    make_float2(acc[mf][nf][0], acc[mf][nf][1]);
            if (row + 8 < N_PTS)
                *(float2*)(C + (size_t)(row + 8) * HDIM + col) =
                    make_float2(acc[mf][nf][2], acc[mf][nf][3]);
        }
    }
}

// -------- assemble stage 1:  h = relu(b1 + 3 gathered taps) -> bf16 hi/lo --
__global__ __launch_bounds__(256)
void assemble1_kernel(const float* __restrict__ b1) {
    int idx = blockIdx.x * 256 + threadIdx.x;      // N_PTS * 72 float4 tasks
    if (idx >= N_PTS * 72) return;
    int p = idx / 72;
    int gidx = idx - p * 72;
    int c = gidx / 24;          // tap 0..2
    int j = gidx - c * 24;      // float4 within 96
    int prev = g_prev[c * N_PTS + p];
    int next = g_next[c * N_PTS + p];
    float4 v = ((const float4*)b1)[j];
    if (prev >= 0) {
        float4 z = *(const float4*)(g_Z + (size_t)prev * HDIM + j * 4);
        v.x += z.x; v.y += z.y; v.z += z.z; v.w += z.w;
    }
    {
        float4 z = *(const float4*)(g_Z + (size_t)p * HDIM + FDIM + j * 4);
        v.x += z.x; v.y += z.y; v.z += z.z; v.w += z.w;
    }
    if (next >= 0) {
        float4 z = *(const float4*)(g_Z + (size_t)next * HDIM + 2 * FDIM + j * 4);
        v.x += z.x; v.y += z.y; v.z += z.z; v.w += z.w;
    }
    v.x = fmaxf(v.x, 0.f); v.y = fmaxf(v.y, 0.f);
    v.z = fmaxf(v.z, 0.f); v.w = fmaxf(v.w, 0.f);
    uint32_t h0, l0, h1, l1;
    split2(make_float2(v.x, v.y), h0, l0);
    split2(make_float2(v.z, v.w), h1, l1);
    int o = p * 72 + c * 24 + j;                   // uint2 (4-elem) index
    ((uint2*)g_hh)[o] = make_uint2(h0, h1);
    ((uint2*)g_hl)[o] = make_uint2(l0, l1);
}

// ------- assemble stage 2 + residual + layernorm (warp per point) ----------
__global__ __launch_bounds__(256)
void assemble2_ln_kernel(const float* __restrict__ b2,
                         const float* __restrict__ gamma,
                         const float* __restrict__ beta,
                         float* __restrict__ out) {
    int p    = (blockIdx.x * 256 + threadIdx.x) >> 5;   // warp per point
    int lane = threadIdx.x & 31;
    float4 xv[3];
    float s = 0.f, q = 0.f;
    if (lane < 24) {
        #pragma unroll
        for (int c = 0; c < 3; c++) {
            int prev = g_prev[c * N_PTS + p];
            int next = g_next[c * N_PTS + p];
            float4 v = ((const float4*)b2)[lane];
            if (prev >= 0) {
                float4 z = *(const float4*)(g_Zh + (size_t)prev * HDIM + lane * 4);
                v.x += z.x; v.y += z.y; v.z += z.z; v.w += z.w;
            }
            {
                float4 z = *(const float4*)(g_Zh + (size_t)p * HDIM + FDIM + lane * 4);
                v.x += z.x; v.y += z.y; v.z += z.z; v.w += z.w;
            }
            if (next >= 0) {
                float4 z = *(const float4*)(g_Zh + (size_t)next * HDIM + 2 * FDIM + lane * 4);
                v.x += z.x; v.y += z.y; v.z += z.z; v.w += z.w;
            }
            int o = p * 72 + c * 24 + lane;
            uint2 hh = ((const uint2*)g_hh)[o];
            uint2 hl = ((const uint2*)g_hl)[o];
            float2 a0 = up2(hh.x), a1 = up2(hh.y);
            float2 b0 = up2(hl.x), b1 = up2(hl.y);
            float4 x;
            x.x = (a0.x + b0.x) + fmaxf(v.x, 0.f);
            x.y = (a0.y + b0.y) + fmaxf(v.y, 0.f);
            x.z = (a1.x + b1.x) + fmaxf(v.z, 0.f);
            x.w = (a1.y + b1.y) + fmaxf(v.w, 0.f);
            xv[c] = x;
            s += x.x + x.y + x.z + x.w;
            q += x.x * x.x + x.y * x.y + x.z * x.z + x.w * x.w;
        }
    }
    #pragma unroll
    for (int o = 16; o > 0; o >>= 1) {
        s += __shfl_xor_sync(0xffffffffu, s, o);
        q += __shfl_xor_sync(0xffffffffu, q, o);
    }
    float mu  = s * (1.f / HDIM);
    float var = q * (1.f / HDIM) - mu * mu;
    float r   = rsqrtf(var + EPSV);
    if (lane < 24) {
        #pragma unroll
        for (int c = 0; c < 3; c++) {
            float4 gm = ((const float4*)gamma)[c * 24 + lane];
            float4 bt = ((const float4*)beta)[c * 24 + lane];
            float4 x  = xv[c];
            float4 o4;
            o4.x = (x.x - mu) * r * gm.x + bt.x;
            o4.y = (x.y - mu) * r * gm.y + bt.y;
            o4.z = (x.z - mu) * r * gm.z + bt.z;
            o4.w = (x.w - mu) * r * gm.w + bt.w;
            *(float4*)(out + (size_t)p * HDIM + c * FDIM + lane * 4) = o4;
        }
    }
}

// ---------------- index pass-through tail ----------------------------------
__global__ void copy_index_kernel(const int* __restrict__ index,
                                  float* __restrict__ out, int count) {
    int t = blockIdx.x * blockDim.x + threadIdx.x;
    if (t < count) out[t] = (float)index[t];
}

// ---------------------------------------------------------------------------
extern "C" void kernel_launch(void* const* d_in, const int* in_sizes, int n_in,
                              void* d_out, int out_size) {
    const float* X     = (const float*)d_in[0];
    const int*   index = (const int*)  d_in[1];
    const float* W1    = (const float*)d_in[2];
    const float* b1    = (const float*)d_in[3];
    const float* W2    = (const float*)d_in[4];
    const float* b2    = (const float*)d_in[5];
    const float* gamma = (const float*)d_in[6];
    const float* beta  = (const float*)d_in[7];
    float* out = (float*)d_out;

    cudaFuncSetAttribute(mma_gemm_kernel<1>,
                         cudaFuncAttributeMaxDynamicSharedMemorySize, GSM_TOTAL);
    cudaFuncSetAttribute(mma_gemm_kernel<2>,
                         cudaFuncAttributeMaxDynamicSharedMemorySize, GSM_TOTAL);

    split_x_kernel<<<(N_PTS * 24 + 255) / 256, 256>>>(X);
    pack_w_kernel<<<(HDIM * HDIM + 255) / 256, 256>>>(W1, W2);
    prevnext_kernel<<<(NCOLS * N_PTS + 255) / 256, 256>>>(index);

    dim3 gg(N_MTILE, 3);
    mma_gemm_kernel<1><<<gg, 256, GSM_TOTAL>>>();        // Z  = X @ B1^T
    assemble1_kernel<<<(N_PTS * 72 + 255) / 256, 256>>>(b1);
    mma_gemm_kernel<2><<<gg, 256, GSM_TOTAL>>>();        // Zh = h @ B2^T
    assemble2_ln_kernel<<<(N_PTS * 32 + 255) / 256, 256>>>(b2, gamma, beta, out);

    int tail = out_size - N_PTS * HDIM;
    if (tail > 0) {
        if (tail > NCOLS * N_PTS) tail = NCOLS * N_PTS;
        copy_index_kernel<<<(tail + 255) / 256, 256>>>(
            index, out + (size_t)N_PTS * HDIM, tail);
    }
}

// round 7
// speedup vs baseline: 1.3420x; 1.0471x over previous
#include <cuda_runtime.h>
#include <cuda_bf16.h>
#include <cstdint>

#define N_PTS 200000
#define CDIM 96
#define FDIM 96
#define NCOLS 3
#define HDIM 288          // NCOLS * FDIM
#define EPSV 1e-3f

// ---------------- scratch (device globals: no allocation allowed) ----------
__device__ float g_Z [(size_t)N_PTS * HDIM];   // stage-1 GEMM out
__device__ float g_Zh[(size_t)N_PTS * HDIM];   // stage-2 GEMM out
__device__ int   g_prev[NCOLS * N_PTS];
__device__ int   g_next[NCOLS * N_PTS];
// A operands pre-split to bf16 hi/lo
__device__ __nv_bfloat16 g_Xh[(size_t)N_PTS * CDIM];
__device__ __nv_bfloat16 g_Xl[(size_t)N_PTS * CDIM];
__device__ __nv_bfloat16 g_hh[(size_t)N_PTS * HDIM];
__device__ __nv_bfloat16 g_hl[(size_t)N_PTS * HDIM];
// bf16-split weights, MMA layout: B[n][k]  (n = tap*FDIM + f, k = input chan)
__device__ __nv_bfloat16 g_B1h[HDIM * CDIM];
__device__ __nv_bfloat16 g_B1l[HDIM * CDIM];
__device__ __nv_bfloat16 g_B2h[HDIM * HDIM];
__device__ __nv_bfloat16 g_B2l[HDIM * HDIM];

// ======================= helpers ==========================================
__device__ __forceinline__ uint32_t smem_u32(const void* p) {
    uint32_t a;
    asm("{ .reg .u64 t; cvta.to.shared.u64 t, %1; cvt.u32.u64 %0, t; }"
        : "=r"(a) : "l"(p));
    return a;
}
__device__ __forceinline__ void cp16(uint32_t dst, const void* src) {
    asm volatile("cp.async.ca.shared.global [%0], [%1], 16;"
                 :: "r"(dst), "l"(src) : "memory");
}
__device__ __forceinline__ void cp16p(uint32_t dst, const void* src, uint32_t sz) {
    asm volatile("cp.async.ca.shared.global [%0], [%1], 16, %2;"
                 :: "r"(dst), "l"(src), "r"(sz) : "memory");
}
#define CP_COMMIT() asm volatile("cp.async.commit_group;" ::: "memory")

__device__ __forceinline__ void ldm_x4(uint32_t* r, uint32_t addr) {
    asm volatile("ldmatrix.sync.aligned.m8n8.x4.shared.b16 {%0,%1,%2,%3}, [%4];"
                 : "=r"(r[0]), "=r"(r[1]), "=r"(r[2]), "=r"(r[3]) : "r"(addr));
}

// D += A*B  (m16n8k16, bf16 in, fp32 acc)
__device__ __forceinline__ void mma_bf16(float* d, const uint32_t* a,
                                         const uint32_t* b) {
    asm volatile(
        "mma.sync.aligned.m16n8k16.row.col.f32.bf16.bf16.f32 "
        "{%0,%1,%2,%3}, {%4,%5,%6,%7}, {%8,%9}, {%0,%1,%2,%3};"
        : "+f"(d[0]), "+f"(d[1]), "+f"(d[2]), "+f"(d[3])
        : "r"(a[0]), "r"(a[1]), "r"(a[2]), "r"(a[3]), "r"(b[0]), "r"(b[1]));
}

// fp32 pair -> bf16x2 hi + bf16x2 lo (residual)
__device__ __forceinline__ void split2(float2 v, uint32_t& hi, uint32_t& lo) {
    uint32_t h;
    asm("cvt.rn.bf16x2.f32 %0, %1, %2;" : "=r"(h) : "f"(v.y), "f"(v.x));
    float hx = __uint_as_float(h << 16);
    float hy = __uint_as_float(h & 0xFFFF0000u);
    float rx = v.x - hx, ry = v.y - hy;
    uint32_t l;
    asm("cvt.rn.bf16x2.f32 %0, %1, %2;" : "=r"(l) : "f"(ry), "f"(rx));
    hi = h; lo = l;
}
// bf16x2 word -> float2 (exact)
__device__ __forceinline__ float2 up2(uint32_t u) {
    return make_float2(__uint_as_float(u << 16),
                       __uint_as_float(u & 0xFFFF0000u));
}

// ---------------- split X into bf16 hi/lo ----------------------------------
__global__ void split_x_kernel(const float* __restrict__ X) {
    int idx = blockIdx.x * 256 + threadIdx.x;        // groups of 4 floats
    if (idx >= N_PTS * (CDIM / 4)) return;
    float4 v = ((const float4*)X)[idx];
    uint32_t h0, l0, h1, l1;
    split2(make_float2(v.x, v.y), h0, l0);
    split2(make_float2(v.z, v.w), h1, l1);
    ((uint2*)g_Xh)[idx] = make_uint2(h0, h1);
    ((uint2*)g_Xl)[idx] = make_uint2(l0, l1);
}

// ---------------- pack weights: bf16 hi/lo split, [n][k] MMA layout --------
__global__ void pack_w_kernel(const float* __restrict__ W1,
                              const float* __restrict__ W2) {
    int t = blockIdx.x * blockDim.x + threadIdx.x;
    if (t < HDIM * HDIM) {                       // W2: (3, 288, 96)
        int n = t / HDIM, k = t % HDIM;
        int tap = n / FDIM, f = n % FDIM;
        float w = W2[((size_t)tap * HDIM + k) * FDIM + f];
        __nv_bfloat16 hi = __float2bfloat16_rn(w);
        g_B2h[(size_t)n * HDIM + k] = hi;
        g_B2l[(size_t)n * HDIM + k] = __float2bfloat16_rn(w - __bfloat162float(hi));
    }
    if (t < HDIM * CDIM) {                       // W1: (3, 96, 96)
        int n = t / CDIM, k = t % CDIM;
        int tap = n / FDIM, f = n % FDIM;
        float w = W1[((size_t)tap * CDIM + k) * FDIM + f];
        __nv_bfloat16 hi = __float2bfloat16_rn(w);
        g_B1h[(size_t)n * CDIM + k] = hi;
        g_B1l[(size_t)n * CDIM + k] = __float2bfloat16_rn(w - __bfloat162float(hi));
    }
}

// ---------------- neighbor maps --------------------------------------------
__global__ void prevnext_kernel(const int* __restrict__ index) {
    int t = blockIdx.x * blockDim.x + threadIdx.x;
    if (t >= NCOLS * N_PTS) return;
    int i = t / NCOLS;
    int c = t % NCOLS;
    int p = index[t];
    g_prev[c * N_PTS + p] = (i > 0)         ? index[t - NCOLS] : -1;
    g_next[c * N_PTS + p] = (i < N_PTS - 1) ? index[t + NCOLS] : -1;
}

// ============== split-bf16 HMMA GEMM:  C[M,288] = A[M,K] @ B[288,K]^T ======
// CTA: BM=128, BN=96, BK=32. 8 warps 4(M) x 2(N); warp tile 32x48 (48 acc).
// A pre-split bf16 hi/lo in gmem. 2-stage cp.async pipeline; ldmatrix frags.
// smem per buf: Ah 128x80B, Al 128x80B, Bh 96x80B, Bl 96x80B = 35840 B.
#define BUF_SZ   35840
#define AL_OFF   10240
#define BH_OFF   20480
#define BL_OFF   28160
#define GSM_TOTAL (2 * BUF_SZ)       // 71680 -> 2 CTAs/SM
#define N_MTILE  1563                // ceil(200000/128)

template <int KDIM>
__device__ __forceinline__ void gemm_stage(
        int tid, int row0, int col0, int k0, int buf,
        const __nv_bfloat16* __restrict__ Ahp,
        const __nv_bfloat16* __restrict__ Alp,
        const __nv_bfloat16* __restrict__ Bhp,
        const __nv_bfloat16* __restrict__ Blp,
        uint32_t sb) {
    uint32_t base = sb + buf * BUF_SZ;
    // A: 128 rows x 32 k bf16 = 512 x 16B per array; 2 per thread per array
    #pragma unroll
    for (int i = 0; i < 2; i++) {
        int cid = tid + i * 256;
        int r = cid >> 2, c = cid & 3;
        int gr = row0 + r;
        uint32_t sz = (gr < N_PTS) ? 16u : 0u;
        size_t go = (size_t)gr * KDIM + k0 + c * 8;
        uint32_t so = (uint32_t)(r * 80 + c * 16);
        cp16p(base + so,          Ahp + go, sz);
        cp16p(base + AL_OFF + so, Alp + go, sz);
    }
    // B: 96 rows x 32 k = 384 x 16B per array
    for (int idx = tid; idx < 384; idx += 256) {
        int r = idx >> 2, c = idx & 3;
        size_t go = (size_t)(col0 + r) * KDIM + k0 + c * 8;
        uint32_t so = (uint32_t)(r * 80 + c * 16);
        cp16(base + BH_OFF + so, Bhp + go);
        cp16(base + BL_OFF + so, Blp + go);
    }
}

template <int STAGE>
__global__ __launch_bounds__(256, 2)
void mma_gemm_kernel() {
    constexpr int KDIM = (STAGE == 1) ? CDIM : HDIM;
    constexpr int NCH  = KDIM / 32;
    const __nv_bfloat16* __restrict__ Ahp = (STAGE == 1) ? g_Xh : g_hh;
    const __nv_bfloat16* __restrict__ Alp = (STAGE == 1) ? g_Xl : g_hl;
    const __nv_bfloat16* __restrict__ Bhp = (STAGE == 1) ? g_B1h : g_B2h;
    const __nv_bfloat16* __restrict__ Blp = (STAGE == 1) ? g_B1l : g_B2l;
    float* __restrict__ C = (STAGE == 1) ? g_Z : g_Zh;

    extern __shared__ char smem[];
    const uint32_t sb = smem_u32(smem);

    const int tid  = threadIdx.x;
    const int wid  = tid >> 5;
    const int lane = tid & 31;
    const int g    = lane >> 2;        // 0..7
    const int tg   = lane & 3;         // 0..3
    const int wm   = wid & 3;          // M warp 0..3
    const int wn   = wid >> 2;         // N warp 0..1
    const int row0 = blockIdx.x * 128;
    const int col0 = blockIdx.y * 96;

    // ldmatrix lane addressing (byte offsets within a buffer)
    //  A .x4: m0 rows0-7@k0, m1 rows8-15@k0, m2 rows0-7@k8, m3 rows8-15@k8
    const uint32_t a_lrow = (uint32_t)(wm * 32 + (lane & 15));
    const uint32_t a_loff = a_lrow * 80 + ((lane >> 4) * 16);
    //  B .x4 over an nf-pair: m0 n0-7@k0, m1 n0-7@k8, m2 n8-15@k0, m3 n8-15@k8
    const uint32_t b_lrow = (uint32_t)(wn * 48 + (lane & 7) + (((lane >> 4) & 1) * 8));
    const uint32_t b_loff = b_lrow * 80 + (((lane >> 3) & 1) * 16);

    float acc[2][6][4];
    #pragma unroll
    for (int mf = 0; mf < 2; mf++)
        #pragma unroll
        for (int nf = 0; nf < 6; nf++)
            #pragma unroll
            for (int i = 0; i < 4; i++) acc[mf][nf][i] = 0.f;

    gemm_stage<KDIM>(tid, row0, col0, 0, 0, Ahp, Alp, Bhp, Blp, sb);
    CP_COMMIT();

    for (int kc = 0; kc < NCH; kc++) {
        if (kc + 1 < NCH) {
            gemm_stage<KDIM>(tid, row0, col0, (kc + 1) * 32, (kc + 1) & 1,
                             Ahp, Alp, Bhp, Blp, sb);
            CP_COMMIT();
            asm volatile("cp.async.wait_group 1;" ::: "memory");
        } else {
            asm volatile("cp.async.wait_group 0;" ::: "memory");
        }
        __syncthreads();

        const uint32_t base = sb + (kc & 1) * BUF_SZ;

        #pragma unroll
        for (int ks = 0; ks < 2; ks++) {
            const uint32_t kb = ks * 32;           // 16 bf16 = 32 bytes
            uint32_t AH[2][4], AL[2][4];
            #pragma unroll
            for (int mf = 0; mf < 2; mf++) {
                uint32_t ad = base + a_loff + mf * (16 * 80) + kb;
                ldm_x4(AH[mf], ad);
                ldm_x4(AL[mf], ad + AL_OFF);
            }
            #pragma unroll
            for (int pnf = 0; pnf < 3; pnf++) {
                uint32_t bd = base + BH_OFF + b_loff + pnf * (16 * 80) + kb;
                uint32_t BH4[4], BL4[4];
                ldm_x4(BH4, bd);
                ldm_x4(BL4, bd + (BL_OFF - BH_OFF));
                #pragma unroll
                for (int half = 0; half < 2; half++) {
                    const uint32_t* bh = BH4 + half * 2;
                    const uint32_t* bl = BL4 + half * 2;
                    float* a0 = acc[0][pnf * 2 + half];
                    float* a1 = acc[1][pnf * 2 + half];
                    mma_bf16(a0, AH[0], bh);
                    mma_bf16(a0, AH[0], bl);
                    mma_bf16(a0, AL[0], bh);
                    mma_bf16(a1, AH[1], bh);
                    mma_bf16(a1, AH[1], bl);
                    mma_bf16(a1, AL[1], bh);
                }
            }
        }
        __syncthreads();
    }

    // epilogue: fp32 accumulators -> C
    #pragma unroll
    for (int mf = 0; mf < 2; mf++) {
        int row = row0 + wm * 32 + mf * 16 + g;
        #pragma unroll
        for (int nf = 0; nf < 6; nf++) {
            int col = col0 + wn * 48 + nf * 8 + 2 * tg;
            if (row < N_PTS)
                *(float2*)(C + (size_t)row * HDIM + col) =
                    make_float2(acc[mf][nf][0], acc[mf][nf][1]);
            if (row + 8 < N_PTS)
                *(float2*)(C + (size_t)(row + 8) * HDIM + col) =
                    make_float2(acc[mf][nf][2], acc[mf][nf][3]);
        }
    }
}

// -------- assemble stage 1:  h = relu(b1 + 3 gathered taps) -> bf16 hi/lo --
__global__ __launch_bounds__(256)
void assemble1_kernel(const float* __restrict__ b1) {
    int idx = blockIdx.x * 256 + threadIdx.x;      // N_PTS * 72 float4 tasks
    if (idx >= N_PTS * 72) return;
    int p = idx / 72;
    int gidx = idx - p * 72;
    int c = gidx / 24;          // tap 0..2
    int j = gidx - c * 24;      // float4 within 96
    int prev = g_prev[c * N_PTS + p];
    int next = g_next[c * N_PTS + p];
    float4 v = ((const float4*)b1)[j];
    if (prev >= 0) {
        float4 z = *(const float4*)(g_Z + (size_t)prev * HDIM + j * 4);
        v.x += z.x; v.y += z.y; v.z += z.z; v.w += z.w;
    }
    {
        float4 z = *(const float4*)(g_Z + (size_t)p * HDIM + FDIM + j * 4);
        v.x += z.x; v.y += z.y; v.z += z.z; v.w += z.w;
    }
    if (next >= 0) {
        float4 z = *(const float4*)(g_Z + (size_t)next * HDIM + 2 * FDIM + j * 4);
        v.x += z.x; v.y += z.y; v.z += z.z; v.w += z.w;
    }
    v.x = fmaxf(v.x, 0.f); v.y = fmaxf(v.y, 0.f);
    v.z = fmaxf(v.z, 0.f); v.w = fmaxf(v.w, 0.f);
    uint32_t h0, l0, h1, l1;
    split2(make_float2(v.x, v.y), h0, l0);
    split2(make_float2(v.z, v.w), h1, l1);
    int o = p * 72 + c * 24 + j;                   // uint2 (4-elem) index
    ((uint2*)g_hh)[o] = make_uint2(h0, h1);
    ((uint2*)g_hl)[o] = make_uint2(l0, l1);
}

// ------- assemble stage 2 + residual + layernorm (warp per point) ----------
__global__ __launch_bounds__(256)
void assemble2_ln_kernel(const float* __restrict__ b2,
                         const float* __restrict__ gamma,
                         const float* __restrict__ beta,
                         float* __restrict__ out) {
    int p    = (blockIdx.x * 256 + threadIdx.x) >> 5;   // warp per point
    int lane = threadIdx.x & 31;
    float4 xv[3];
    float s = 0.f, q = 0.f;
    if (lane < 24) {
        #pragma unroll
        for (int c = 0; c < 3; c++) {
            int prev = g_prev[c * N_PTS + p];
            int next = g_next[c * N_PTS + p];
            float4 v = ((const float4*)b2)[lane];
            if (prev >= 0) {
                float4 z = *(const float4*)(g_Zh + (size_t)prev * HDIM + lane * 4);
                v.x += z.x; v.y += z.y; v.z += z.z; v.w += z.w;
            }
            {
                float4 z = *(const float4*)(g_Zh + (size_t)p * HDIM + FDIM + lane * 4);
                v.x += z.x; v.y += z.y; v.z += z.z; v.w += z.w;
            }
            if (next >= 0) {
                float4 z = *(const float4*)(g_Zh + (size_t)next * HDIM + 2 * FDIM + lane * 4);
                v.x += z.x; v.y += z.y; v.z += z.z; v.w += z.w;
            }
            int o = p * 72 + c * 24 + lane;
            uint2 hh = ((const uint2*)g_hh)[o];
            uint2 hl = ((const uint2*)g_hl)[o];
            float2 a0 = up2(hh.x), a1 = up2(hh.y);
            float2 b0 = up2(hl.x), b1 = up2(hl.y);
            float4 x;
            x.x = (a0.x + b0.x) + fmaxf(v.x, 0.f);
            x.y = (a0.y + b0.y) + fmaxf(v.y, 0.f);
            x.z = (a1.x + b1.x) + fmaxf(v.z, 0.f);
            x.w = (a1.y + b1.y) + fmaxf(v.w, 0.f);
            xv[c] = x;
            s += x.x + x.y + x.z + x.w;
            q += x.x * x.x + x.y * x.y + x.z * x.z + x.w * x.w;
        }
    }
    #pragma unroll
    for (int o = 16; o > 0; o >>= 1) {
        s += __shfl_xor_sync(0xffffffffu, s, o);
        q += __shfl_xor_sync(0xffffffffu, q, o);
    }
    float mu  = s * (1.f / HDIM);
    float var = q * (1.f / HDIM) - mu * mu;
    float r   = rsqrtf(var + EPSV);
    if (lane < 24) {
        #pragma unroll
        for (int c = 0; c < 3; c++) {
            float4 gm = ((const float4*)gamma)[c * 24 + lane];
            float4 bt = ((const float4*)beta)[c * 24 + lane];
            float4 x  = xv[c];
            float4 o4;
            o4.x = (x.x - mu) * r * gm.x + bt.x;
            o4.y = (x.y - mu) * r * gm.y + bt.y;
            o4.z = (x.z - mu) * r * gm.z + bt.z;
            o4.w = (x.w - mu) * r * gm.w + bt.w;
            *(float4*)(out + (size_t)p * HDIM + c * FDIM + lane * 4) = o4;
        }
    }
}

// ---------------- index pass-through tail ----------------------------------
__global__ void copy_index_kernel(const int* __restrict__ index,
                                  float* __restrict__ out, int count) {
    int t = blockIdx.x * blockDim.x + threadIdx.x;
    if (t < count) out[t] = (float)index[t];
}

// ---------------------------------------------------------------------------
extern "C" void kernel_launch(void* const* d_in, const int* in_sizes, int n_in,
                              void* d_out, int out_size) {
    const float* X     = (const float*)d_in[0];
    const int*   index = (const int*)  d_in[1];
    const float* W1    = (const float*)d_in[2];
    const float* b1    = (const float*)d_in[3];
    const float* W2    = (const float*)d_in[4];
    const float* b2    = (const float*)d_in[5];
    const float* gamma = (const float*)d_in[6];
    const float* beta  = (const float*)d_in[7];
    float* out = (float*)d_out;

    cudaFuncSetAttribute(mma_gemm_kernel<1>,
                         cudaFuncAttributeMaxDynamicSharedMemorySize, GSM_TOTAL);
    cudaFuncSetAttribute(mma_gemm_kernel<2>,
                         cudaFuncAttributeMaxDynamicSharedMemorySize, GSM_TOTAL);

    split_x_kernel<<<(N_PTS * 24 + 255) / 256, 256>>>(X);
    pack_w_kernel<<<(HDIM * HDIM + 255) / 256, 256>>>(W1, W2);
    prevnext_kernel<<<(NCOLS * N_PTS + 255) / 256, 256>>>(index);

    dim3 gg(N_MTILE, 3);
    mma_gemm_kernel<1><<<gg, 256, GSM_TOTAL>>>();        // Z  = X @ B1^T
    assemble1_kernel<<<(N_PTS * 72 + 255) / 256, 256>>>(b1);
    mma_gemm_kernel<2><<<gg, 256, GSM_TOTAL>>>();        // Zh = h @ B2^T
    assemble2_ln_kernel<<<(N_PTS * 32 + 255) / 256, 256>>>(b2, gamma, beta, out);

    int tail = out_size - N_PTS * HDIM;
    if (tail > 0) {
        if (tail > NCOLS * N_PTS) tail = NCOLS * N_PTS;
        copy_index_kernel<<<(tail + 255) / 256, 256>>>(
            index, out + (size_t)N_PTS * HDIM, tail);
    }
}

// round 8
// speedup vs baseline: 1.3600x; 1.0134x over previous
#include <cuda_runtime.h>
#include <cuda_bf16.h>
#include <cstdint>

#define N_PTS 200000
#define CDIM 96
#define FDIM 96
#define NCOLS 3
#define HDIM 288          // NCOLS * FDIM
#define EPSV 1e-3f

// ---------------- scratch (device globals: no allocation allowed) ----------
__device__ float g_Z [(size_t)N_PTS * HDIM];   // stage-1 GEMM out
__device__ float g_Zh[(size_t)N_PTS * HDIM];   // stage-2 GEMM out
__device__ int   g_prev[NCOLS * N_PTS];
__device__ int   g_next[NCOLS * N_PTS];
// A operands pre-split to bf16 hi/lo
__device__ __nv_bfloat16 g_Xh[(size_t)N_PTS * CDIM];
__device__ __nv_bfloat16 g_Xl[(size_t)N_PTS * CDIM];
__device__ __nv_bfloat16 g_hh[(size_t)N_PTS * HDIM];
__device__ __nv_bfloat16 g_hl[(size_t)N_PTS * HDIM];
// bf16-split weights, MMA layout: B[n][k]  (n = tap*FDIM + f, k = input chan)
__device__ __nv_bfloat16 g_B1h[HDIM * CDIM];
__device__ __nv_bfloat16 g_B1l[HDIM * CDIM];
__device__ __nv_bfloat16 g_B2h[HDIM * HDIM];
__device__ __nv_bfloat16 g_B2l[HDIM * HDIM];

// ======================= helpers ==========================================
__device__ __forceinline__ uint32_t smem_u32(const void* p) {
    uint32_t a;
    asm("{ .reg .u64 t; cvta.to.shared.u64 t, %1; cvt.u32.u64 %0, t; }"
        : "=r"(a) : "l"(p));
    return a;
}
// .cg: bypass L1 (keep L1 free for ldmatrix traffic)
__device__ __forceinline__ void cp16(uint32_t dst, const void* src) {
    asm volatile("cp.async.cg.shared.global [%0], [%1], 16;"
                 :: "r"(dst), "l"(src) : "memory");
}
__device__ __forceinline__ void cp16p(uint32_t dst, const void* src, uint32_t sz) {
    asm volatile("cp.async.cg.shared.global [%0], [%1], 16, %2;"
                 :: "r"(dst), "l"(src), "r"(sz) : "memory");
}
#define CP_COMMIT() asm volatile("cp.async.commit_group;" ::: "memory")

__device__ __forceinline__ void ldm_x4(uint32_t* r, uint32_t addr) {
    asm volatile("ldmatrix.sync.aligned.m8n8.x4.shared.b16 {%0,%1,%2,%3}, [%4];"
                 : "=r"(r[0]), "=r"(r[1]), "=r"(r[2]), "=r"(r[3]) : "r"(addr));
}

// D += A*B  (m16n8k16, bf16 in, fp32 acc)
__device__ __forceinline__ void mma_bf16(float* d, const uint32_t* a,
                                         const uint32_t* b) {
    asm volatile(
        "mma.sync.aligned.m16n8k16.row.col.f32.bf16.bf16.f32 "
        "{%0,%1,%2,%3}, {%4,%5,%6,%7}, {%8,%9}, {%0,%1,%2,%3};"
        : "+f"(d[0]), "+f"(d[1]), "+f"(d[2]), "+f"(d[3])
        : "r"(a[0]), "r"(a[1]), "r"(a[2]), "r"(a[3]), "r"(b[0]), "r"(b[1]));
}

// fp32 pair -> bf16x2 hi + bf16x2 lo (residual)
__device__ __forceinline__ void split2(float2 v, uint32_t& hi, uint32_t& lo) {
    uint32_t h;
    asm("cvt.rn.bf16x2.f32 %0, %1, %2;" : "=r"(h) : "f"(v.y), "f"(v.x));
    float hx = __uint_as_float(h << 16);
    float hy = __uint_as_float(h & 0xFFFF0000u);
    float rx = v.x - hx, ry = v.y - hy;
    uint32_t l;
    asm("cvt.rn.bf16x2.f32 %0, %1, %2;" : "=r"(l) : "f"(ry), "f"(rx));
    hi = h; lo = l;
}
// bf16x2 word -> float2 (exact)
__device__ __forceinline__ float2 up2(uint32_t u) {
    return make_float2(__uint_as_float(u << 16),
                       __uint_as_float(u & 0xFFFF0000u));
}

// ---------------- split X into bf16 hi/lo ----------------------------------
__global__ void split_x_kernel(const float* __restrict__ X) {
    int idx = blockIdx.x * 256 + threadIdx.x;        // groups of 4 floats
    if (idx >= N_PTS * (CDIM / 4)) return;
    float4 v = ((const float4*)X)[idx];
    uint32_t h0, l0, h1, l1;
    split2(make_float2(v.x, v.y), h0, l0);
    split2(make_float2(v.z, v.w), h1, l1);
    ((uint2*)g_Xh)[idx] = make_uint2(h0, h1);
    ((uint2*)g_Xl)[idx] = make_uint2(l0, l1);
}

// ---------------- pack weights: bf16 hi/lo split, [n][k] MMA layout --------
__global__ void pack_w_kernel(const float* __restrict__ W1,
                              const float* __restrict__ W2) {
    int t = blockIdx.x * blockDim.x + threadIdx.x;
    if (t < HDIM * HDIM) {                       // W2: (3, 288, 96)
        int n = t / HDIM, k = t % HDIM;
        int tap = n / FDIM, f = n % FDIM;
        float w = W2[((size_t)tap * HDIM + k) * FDIM + f];
        __nv_bfloat16 hi = __float2bfloat16_rn(w);
        g_B2h[(size_t)n * HDIM + k] = hi;
        g_B2l[(size_t)n * HDIM + k] = __float2bfloat16_rn(w - __bfloat162float(hi));
    }
    if (t < HDIM * CDIM) {                       // W1: (3, 96, 96)
        int n = t / CDIM, k = t % CDIM;
        int tap = n / FDIM, f = n % FDIM;
        float w = W1[((size_t)tap * CDIM + k) * FDIM + f];
        __nv_bfloat16 hi = __float2bfloat16_rn(w);
        g_B1h[(size_t)n * CDIM + k] = hi;
        g_B1l[(size_t)n * CDIM + k] = __float2bfloat16_rn(w - __bfloat162float(hi));
    }
}

// ---------------- neighbor maps --------------------------------------------
__global__ void prevnext_kernel(const int* __restrict__ index) {
    int t = blockIdx.x * blockDim.x + threadIdx.x;
    if (t >= NCOLS * N_PTS) return;
    int i = t / NCOLS;
    int c = t % NCOLS;
    int p = index[t];
    g_prev[c * N_PTS + p] = (i > 0)         ? index[t - NCOLS] : -1;
    g_next[c * N_PTS + p] = (i < N_PTS - 1) ? index[t + NCOLS] : -1;
}

// ============== split-bf16 HMMA GEMM:  C[M,288] = A[M,K] @ B[288,K]^T ======
// CTA: BM=128, BN=96, BK=32. 12 warps 4(M) x 3(N); warp tile 32x32 (32 acc).
// A pre-split bf16 hi/lo in gmem. 2-stage cp.async pipeline; ldmatrix frags.
// smem per buf: Ah 128x80B, Al 128x80B, Bh 96x80B, Bl 96x80B = 35840 B.
#define BUF_SZ   35840
#define AL_OFF   10240
#define BH_OFF   20480
#define BL_OFF   28160
#define GSM_TOTAL (2 * BUF_SZ)       // 71680 -> 2 CTAs/SM
#define N_MTILE  1563                // ceil(200000/128)
#define NTHR     384

template <int KDIM>
__device__ __forceinline__ void gemm_stage(
        int tid, int row0, int col0, int k0, int buf,
        const __nv_bfloat16* __restrict__ Ahp,
        const __nv_bfloat16* __restrict__ Alp,
        const __nv_bfloat16* __restrict__ Bhp,
        const __nv_bfloat16* __restrict__ Blp,
        uint32_t sb) {
    uint32_t base = sb + buf * BUF_SZ;
    // A: 128 rows x 32 k bf16 = 512 x 16B per array
    for (int idx = tid; idx < 512; idx += NTHR) {
        int r = idx >> 2, c = idx & 3;
        int gr = row0 + r;
        uint32_t sz = (gr < N_PTS) ? 16u : 0u;
        size_t go = (size_t)gr * KDIM + k0 + c * 8;
        uint32_t so = (uint32_t)(r * 80 + c * 16);
        cp16p(base + so,          Ahp + go, sz);
        cp16p(base + AL_OFF + so, Alp + go, sz);
    }
    // B: 96 rows x 32 k = 384 x 16B per array; exactly one per thread
    {
        int idx = tid;
        int r = idx >> 2, c = idx & 3;
        size_t go = (size_t)(col0 + r) * KDIM + k0 + c * 8;
        uint32_t so = (uint32_t)(r * 80 + c * 16);
        cp16(base + BH_OFF + so, Bhp + go);
        cp16(base + BL_OFF + so, Blp + go);
    }
}

template <int STAGE>
__global__ __launch_bounds__(NTHR, 2)
void mma_gemm_kernel() {
    constexpr int KDIM = (STAGE == 1) ? CDIM : HDIM;
    constexpr int NCH  = KDIM / 32;
    const __nv_bfloat16* __restrict__ Ahp = (STAGE == 1) ? g_Xh : g_hh;
    const __nv_bfloat16* __restrict__ Alp = (STAGE == 1) ? g_Xl : g_hl;
    const __nv_bfloat16* __restrict__ Bhp = (STAGE == 1) ? g_B1h : g_B2h;
    const __nv_bfloat16* __restrict__ Blp = (STAGE == 1) ? g_B1l : g_B2l;
    float* __restrict__ C = (STAGE == 1) ? g_Z : g_Zh;

    extern __shared__ char smem[];
    const uint32_t sb = smem_u32(smem);

    const int tid  = threadIdx.x;
    const int wid  = tid >> 5;
    const int lane = tid & 31;
    const int g    = lane >> 2;        // 0..7
    const int tg   = lane & 3;         // 0..3
    const int wm   = wid & 3;          // M warp 0..3
    const int wn   = wid >> 2;         // N warp 0..2
    const int row0 = blockIdx.x * 128;
    const int col0 = blockIdx.y * 96;

    // ldmatrix lane addressing (byte offsets within a buffer)
    const uint32_t a_lrow = (uint32_t)(wm * 32 + (lane & 15));
    const uint32_t a_loff = a_lrow * 80 + ((lane >> 4) * 16);
    const uint32_t b_lrow = (uint32_t)(wn * 32 + (lane & 7) + (((lane >> 4) & 1) * 8));
    const uint32_t b_loff = b_lrow * 80 + (((lane >> 3) & 1) * 16);

    float acc[2][4][4];
    #pragma unroll
    for (int mf = 0; mf < 2; mf++)
        #pragma unroll
        for (int nf = 0; nf < 4; nf++)
            #pragma unroll
            for (int i = 0; i < 4; i++) acc[mf][nf][i] = 0.f;

    gemm_stage<KDIM>(tid, row0, col0, 0, 0, Ahp, Alp, Bhp, Blp, sb);
    CP_COMMIT();

    for (int kc = 0; kc < NCH; kc++) {
        if (kc + 1 < NCH) {
            gemm_stage<KDIM>(tid, row0, col0, (kc + 1) * 32, (kc + 1) & 1,
                             Ahp, Alp, Bhp, Blp, sb);
            CP_COMMIT();
            asm volatile("cp.async.wait_group 1;" ::: "memory");
        } else {
            asm volatile("cp.async.wait_group 0;" ::: "memory");
        }
        __syncthreads();

        const uint32_t base = sb + (kc & 1) * BUF_SZ;

        #pragma unroll
        for (int ks = 0; ks < 2; ks++) {
            const uint32_t kb = ks * 32;           // 16 bf16 = 32 bytes
            uint32_t AH[2][4], AL[2][4];
            #pragma unroll
            for (int mf = 0; mf < 2; mf++) {
                uint32_t ad = base + a_loff + mf * (16 * 80) + kb;
                ldm_x4(AH[mf], ad);
                ldm_x4(AL[mf], ad + AL_OFF);
            }
            #pragma unroll
            for (int pnf = 0; pnf < 2; pnf++) {
                uint32_t bd = base + BH_OFF + b_loff + pnf * (16 * 80) + kb;
                uint32_t BH4[4], BL4[4];
                ldm_x4(BH4, bd);
                ldm_x4(BL4, bd + (BL_OFF - BH_OFF));
                #pragma unroll
                for (int half = 0; half < 2; half++) {
                    const uint32_t* bh = BH4 + half * 2;
                    const uint32_t* bl = BL4 + half * 2;
                    float* a0 = acc[0][pnf * 2 + half];
                    float* a1 = acc[1][pnf * 2 + half];
                    mma_bf16(a0, AH[0], bh);
                    mma_bf16(a0, AH[0], bl);
                    mma_bf16(a0, AL[0], bh);
                    mma_bf16(a1, AH[1], bh);
                    mma_bf16(a1, AH[1], bl);
                    mma_bf16(a1, AL[1], bh);
                }
            }
        }
        __syncthreads();
    }

    // epilogue: fp32 accumulators -> C
    #pragma unroll
    for (int mf = 0; mf < 2; mf++) {
        int row = row0 + wm * 32 + mf * 16 + g;
        #pragma unroll
        for (int nf = 0; nf < 4; nf++) {
            int col = col0 + wn * 32 + nf * 8 + 2 * tg;
            if (row < N_PTS)
                *(float2*)(C + (size_t)row * HDIM + col) =
                    make_float2(acc[mf][nf][0], acc[mf][nf][1]);
            if (row + 8 < N_PTS)
                *(float2*)(C + (size_t)(row + 8) * HDIM + col) =
                    make_float2(acc[mf][nf][2], acc[mf][nf][3]);
        }
    }
}

// -------- assemble stage 1:  h = relu(b1 + 3 gathered taps) -> bf16 hi/lo --
__global__ __launch_bounds__(256)
void assemble1_kernel(const float* __restrict__ b1) {
    int idx = blockIdx.x * 256 + threadIdx.x;      // N_PTS * 72 float4 tasks
    if (idx >= N_PTS * 72) return;
    int p = idx / 72;
    int gidx = idx - p * 72;
    int c = gidx / 24;          // tap 0..2
    int j = gidx - c * 24;      // float4 within 96
    int prev = g_prev[c * N_PTS + p];
    int next = g_next[c * N_PTS + p];
    float4 v = ((const float4*)b1)[j];
    if (prev >= 0) {
        float4 z = *(const float4*)(g_Z + (size_t)prev * HDIM + j * 4);
        v.x += z.x; v.y += z.y; v.z += z.z; v.w += z.w;
    }
    {
        float4 z = *(const float4*)(g_Z + (size_t)p * HDIM + FDIM + j * 4);
        v.x += z.x; v.y += z.y; v.z += z.z; v.w += z.w;
    }
    if (next >= 0) {
        float4 z = *(const float4*)(g_Z + (size_t)next * HDIM + 2 * FDIM + j * 4);
        v.x += z.x; v.y += z.y; v.z += z.z; v.w += z.w;
    }
    v.x = fmaxf(v.x, 0.f); v.y = fmaxf(v.y, 0.f);
    v.z = fmaxf(v.z, 0.f); v.w = fmaxf(v.w, 0.f);
    uint32_t h0, l0, h1, l1;
    split2(make_float2(v.x, v.y), h0, l0);
    split2(make_float2(v.z, v.w), h1, l1);
    int o = p * 72 + c * 24 + j;                   // uint2 (4-elem) index
    ((uint2*)g_hh)[o] = make_uint2(h0, h1);
    ((uint2*)g_hl)[o] = make_uint2(l0, l1);
}

// ------- assemble stage 2 + residual + layernorm (warp per point) ----------
__global__ __launch_bounds__(256)
void assemble2_ln_kernel(const float* __restrict__ b2,
                         const float* __restrict__ gamma,
                         const float* __restrict__ beta,
                         float* __restrict__ out) {
    int p    = (blockIdx.x * 256 + threadIdx.x) >> 5;   // warp per point
    int lane = threadIdx.x & 31;
    float4 xv[3];
    float s = 0.f, q = 0.f;
    if (lane < 24) {
        #pragma unroll
        for (int c = 0; c < 3; c++) {
            int prev = g_prev[c * N_PTS + p];
            int next = g_next[c * N_PTS + p];
            float4 v = ((const float4*)b2)[lane];
            if (prev >= 0) {
                float4 z = *(const float4*)(g_Zh + (size_t)prev * HDIM + lane * 4);
                v.x += z.x; v.y += z.y; v.z += z.z; v.w += z.w;
            }
            {
                float4 z = *(const float4*)(g_Zh + (size_t)p * HDIM + FDIM + lane * 4);
                v.x += z.x; v.y += z.y; v.z += z.z; v.w += z.w;
            }
            if (next >= 0) {
                float4 z = *(const float4*)(g_Zh + (size_t)next * HDIM + 2 * FDIM + lane * 4);
                v.x += z.x; v.y += z.y; v.z += z.z; v.w += z.w;
            }
            int o = p * 72 + c * 24 + lane;
            uint2 hh = ((const uint2*)g_hh)[o];
            uint2 hl = ((const uint2*)g_hl)[o];
            float2 a0 = up2(hh.x), a1 = up2(hh.y);
            float2 b0 = up2(hl.x), b1 = up2(hl.y);
            float4 x;
            x.x = (a0.x + b0.x) + fmaxf(v.x, 0.f);
            x.y = (a0.y + b0.y) + fmaxf(v.y, 0.f);
            x.z = (a1.x + b1.x) + fmaxf(v.z, 0.f);
            x.w = (a1.y + b1.y) + fmaxf(v.w, 0.f);
            xv[c] = x;
            s += x.x + x.y + x.z + x.w;
            q += x.x * x.x + x.y * x.y + x.z * x.z + x.w * x.w;
        }
    }
    #pragma unroll
    for (int o = 16; o > 0; o >>= 1) {
        s += __shfl_xor_sync(0xffffffffu, s, o);
        q += __shfl_xor_sync(0xffffffffu, q, o);
    }
    float mu  = s * (1.f / HDIM);
    float var = q * (1.f / HDIM) - mu * mu;
    float r   = rsqrtf(var + EPSV);
    if (lane < 24) {
        #pragma unroll
        for (int c = 0; c < 3; c++) {
            float4 gm = ((const float4*)gamma)[c * 24 + lane];
            float4 bt = ((const float4*)beta)[c * 24 + lane];
            float4 x  = xv[c];
            float4 o4;
            o4.x = (x.x - mu) * r * gm.x + bt.x;
            o4.y = (x.y - mu) * r * gm.y + bt.y;
            o4.z = (x.z - mu) * r * gm.z + bt.z;
            o4.w = (x.w - mu) * r * gm.w + bt.w;
            *(float4*)(out + (size_t)p * HDIM + c * FDIM + lane * 4) = o4;
        }
    }
}

// ---------------- index pass-through tail ----------------------------------
__global__ void copy_index_kernel(const int* __restrict__ index,
                                  float* __restrict__ out, int count) {
    int t = blockIdx.x * blockDim.x + threadIdx.x;
    if (t < count) out[t] = (float)index[t];
}

// ---------------------------------------------------------------------------
extern "C" void kernel_launch(void* const* d_in, const int* in_sizes, int n_in,
                              void* d_out, int out_size) {
    const float* X     = (const float*)d_in[0];
    const int*   index = (const int*)  d_in[1];
    const float* W1    = (const float*)d_in[2];
    const float* b1    = (const float*)d_in[3];
    const float* W2    = (const float*)d_in[4];
    const float* b2    = (const float*)d_in[5];
    const float* gamma = (const float*)d_in[6];
    const float* beta  = (const float*)d_in[7];
    float* out = (float*)d_out;

    cudaFuncSetAttribute(mma_gemm_kernel<1>,
                         cudaFuncAttributeMaxDynamicSharedMemorySize, GSM_TOTAL);
    cudaFuncSetAttribute(mma_gemm_kernel<2>,
                         cudaFuncAttributeMaxDynamicSharedMemorySize, GSM_TOTAL);

    split_x_kernel<<<(N_PTS * 24 + 255) / 256, 256>>>(X);
    pack_w_kernel<<<(HDIM * HDIM + 255) / 256, 256>>>(W1, W2);
    prevnext_kernel<<<(NCOLS * N_PTS + 255) / 256, 256>>>(index);

    dim3 gg(N_MTILE, 3);
    mma_gemm_kernel<1><<<gg, NTHR, GSM_TOTAL>>>();        // Z  = X @ B1^T
    assemble1_kernel<<<(N_PTS * 72 + 255) / 256, 256>>>(b1);
    mma_gemm_kernel<2><<<gg, NTHR, GSM_TOTAL>>>();        // Zh = h @ B2^T
    assemble2_ln_kernel<<<(N_PTS * 32 + 255) / 256, 256>>>(b2, gamma, beta, out);

    int tail = out_size - N_PTS * HDIM;
    if (tail > 0) {
        if (tail > NCOLS * N_PTS) tail = NCOLS * N_PTS;
        copy_index_kernel<<<(tail + 255) / 256, 256>>>(
            index, out + (size_t)N_PTS * HDIM, tail);
    }
}

// round 9
// speedup vs baseline: 1.5335x; 1.1276x over previous
#include <cuda_runtime.h>
#include <cuda_fp16.h>
#include <cstdint>

#define N_PTS 200000
#define CDIM 96
#define FDIM 96
#define NCOLS 3
#define HDIM 288          // NCOLS * FDIM
#define EPSV 1e-3f

// ---------------- scratch (device globals: no allocation allowed) ----------
__device__ float g_Z [(size_t)N_PTS * HDIM];   // stage-1 GEMM out
__device__ float g_Zh[(size_t)N_PTS * HDIM];   // stage-2 GEMM out
__device__ int   g_prev[NCOLS * N_PTS];
__device__ int   g_next[NCOLS * N_PTS];
// A operands pre-split to fp16 hi/lo
__device__ __half g_Xh[(size_t)N_PTS * CDIM];
__device__ __half g_Xl[(size_t)N_PTS * CDIM];
__device__ __half g_hh[(size_t)N_PTS * HDIM];
__device__ __half g_hl[(size_t)N_PTS * HDIM];
// fp16 weights (hi only), MMA layout: B[n][k]  (n = tap*FDIM + f)
__device__ __half g_B1h[HDIM * CDIM];
__device__ __half g_B2h[HDIM * HDIM];

// ======================= helpers ==========================================
__device__ __forceinline__ uint32_t smem_u32(const void* p) {
    uint32_t a;
    asm("{ .reg .u64 t; cvta.to.shared.u64 t, %1; cvt.u32.u64 %0, t; }"
        : "=r"(a) : "l"(p));
    return a;
}
// .cg: bypass L1 (keep L1 free for ldmatrix traffic)
__device__ __forceinline__ void cp16(uint32_t dst, const void* src) {
    asm volatile("cp.async.cg.shared.global [%0], [%1], 16;"
                 :: "r"(dst), "l"(src) : "memory");
}
__device__ __forceinline__ void cp16p(uint32_t dst, const void* src, uint32_t sz) {
    asm volatile("cp.async.cg.shared.global [%0], [%1], 16, %2;"
                 :: "r"(dst), "l"(src), "r"(sz) : "memory");
}
#define CP_COMMIT() asm volatile("cp.async.commit_group;" ::: "memory")

__device__ __forceinline__ void ldm_x4(uint32_t* r, uint32_t addr) {
    asm volatile("ldmatrix.sync.aligned.m8n8.x4.shared.b16 {%0,%1,%2,%3}, [%4];"
                 : "=r"(r[0]), "=r"(r[1]), "=r"(r[2]), "=r"(r[3]) : "r"(addr));
}

// D += A*B  (m16n8k16, fp16 in, fp32 acc)
__device__ __forceinline__ void mma_f16(float* d, const uint32_t* a,
                                        const uint32_t* b) {
    asm volatile(
        "mma.sync.aligned.m16n8k16.row.col.f32.f16.f16.f32 "
        "{%0,%1,%2,%3}, {%4,%5,%6,%7}, {%8,%9}, {%0,%1,%2,%3};"
        : "+f"(d[0]), "+f"(d[1]), "+f"(d[2]), "+f"(d[3])
        : "r"(a[0]), "r"(a[1]), "r"(a[2]), "r"(a[3]), "r"(b[0]), "r"(b[1]));
}

// fp32 pair -> f16x2 hi + f16x2 lo (residual)
__device__ __forceinline__ void split2(float2 v, uint32_t& hi, uint32_t& lo) {
    __half2 h = __floats2half2_rn(v.x, v.y);
    float2 hf = __half22float2(h);
    __half2 l = __floats2half2_rn(v.x - hf.x, v.y - hf.y);
    hi = *reinterpret_cast<uint32_t*>(&h);
    lo = *reinterpret_cast<uint32_t*>(&l);
}
// f16x2 word -> float2 (exact)
__device__ __forceinline__ float2 up2(uint32_t u) {
    __half2 h = *reinterpret_cast<__half2*>(&u);
    return __half22float2(h);
}

// ---------------- split X into fp16 hi/lo ----------------------------------
__global__ void split_x_kernel(const float* __restrict__ X) {
    int idx = blockIdx.x * 256 + threadIdx.x;        // groups of 4 floats
    if (idx >= N_PTS * (CDIM / 4)) return;
    float4 v = ((const float4*)X)[idx];
    uint32_t h0, l0, h1, l1;
    split2(make_float2(v.x, v.y), h0, l0);
    split2(make_float2(v.z, v.w), h1, l1);
    ((uint2*)g_Xh)[idx] = make_uint2(h0, h1);
    ((uint2*)g_Xl)[idx] = make_uint2(l0, l1);
}

// ---------------- pack weights: fp16 (hi), [n][k] MMA layout ---------------
__global__ void pack_w_kernel(const float* __restrict__ W1,
                              const float* __restrict__ W2) {
    int t = blockIdx.x * blockDim.x + threadIdx.x;
    if (t < HDIM * HDIM) {                       // W2: (3, 288, 96)
        int n = t / HDIM, k = t % HDIM;
        int tap = n / FDIM, f = n % FDIM;
        g_B2h[(size_t)n * HDIM + k] =
            __float2half_rn(W2[((size_t)tap * HDIM + k) * FDIM + f]);
    }
    if (t < HDIM * CDIM) {                       // W1: (3, 96, 96)
        int n = t / CDIM, k = t % CDIM;
        int tap = n / FDIM, f = n % FDIM;
        g_B1h[(size_t)n * CDIM + k] =
            __float2half_rn(W1[((size_t)tap * CDIM + k) * FDIM + f]);
    }
}

// ---------------- neighbor maps --------------------------------------------
__global__ void prevnext_kernel(const int* __restrict__ index) {
    int t = blockIdx.x * blockDim.x + threadIdx.x;
    if (t >= NCOLS * N_PTS) return;
    int i = t / NCOLS;
    int c = t % NCOLS;
    int p = index[t];
    g_prev[c * N_PTS + p] = (i > 0)         ? index[t - NCOLS] : -1;
    g_next[c * N_PTS + p] = (i < N_PTS - 1) ? index[t + NCOLS] : -1;
}

// ============ split-fp16 HMMA GEMM:  C[M,288] = A[M,K] @ B[288,K]^T ========
// 2-pass: C = (Ah + Al) @ Bh^T   (dropped A@Bl ~ 2^-11 relative)
// CTA: BM=128, BN=96, BK=32. 12 warps 4(M) x 3(N); warp tile 32x32 (32 acc).
// smem per buf: Ah 128x80B, Al 128x80B, Bh 96x80B = 28160 B.
#define BUF_SZ   28160
#define AL_OFF   10240
#define BH_OFF   20480
#define GSM_TOTAL (2 * BUF_SZ)       // 56320 -> 2 CTAs/SM
#define N_MTILE  1563                // ceil(200000/128)
#define NTHR     384

template <int KDIM>
__device__ __forceinline__ void gemm_stage(
        int tid, int row0, int col0, int k0, int buf,
        const __half* __restrict__ Ahp,
        const __half* __restrict__ Alp,
        const __half* __restrict__ Bhp,
        uint32_t sb) {
    uint32_t base = sb + buf * BUF_SZ;
    // A: 128 rows x 32 k fp16 = 512 x 16B per array
    for (int idx = tid; idx < 512; idx += NTHR) {
        int r = idx >> 2, c = idx & 3;
        int gr = row0 + r;
        uint32_t sz = (gr < N_PTS) ? 16u : 0u;
        size_t go = (size_t)gr * KDIM + k0 + c * 8;
        uint32_t so = (uint32_t)(r * 80 + c * 16);
        cp16p(base + so,          Ahp + go, sz);
        cp16p(base + AL_OFF + so, Alp + go, sz);
    }
    // B: 96 rows x 32 k = 384 x 16B; exactly one per thread
    {
        int r = tid >> 2, c = tid & 3;
        size_t go = (size_t)(col0 + r) * KDIM + k0 + c * 8;
        cp16(base + BH_OFF + (uint32_t)(r * 80 + c * 16), Bhp + go);
    }
}

template <int STAGE>
__global__ __launch_bounds__(NTHR, 2)
void mma_gemm_kernel() {
    constexpr int KDIM = (STAGE == 1) ? CDIM : HDIM;
    constexpr int NCH  = KDIM / 32;
    const __half* __restrict__ Ahp = (STAGE == 1) ? g_Xh : g_hh;
    const __half* __restrict__ Alp = (STAGE == 1) ? g_Xl : g_hl;
    const __half* __restrict__ Bhp = (STAGE == 1) ? g_B1h : g_B2h;
    float* __restrict__ C = (STAGE == 1) ? g_Z : g_Zh;

    extern __shared__ char smem[];
    const uint32_t sb = smem_u32(smem);

    const int tid  = threadIdx.x;
    const int wid  = tid >> 5;
    const int lane = tid & 31;
    const int g    = lane >> 2;        // 0..7
    const int tg   = lane & 3;         // 0..3
    const int wm   = wid & 3;          // M warp 0..3
    const int wn   = wid >> 2;         // N warp 0..2
    const int row0 = blockIdx.x * 128;
    const int col0 = blockIdx.y * 96;

    // ldmatrix lane addressing (byte offsets within a buffer)
    const uint32_t a_lrow = (uint32_t)(wm * 32 + (lane & 15));
    const uint32_t a_loff = a_lrow * 80 + ((lane >> 4) * 16);
    const uint32_t b_lrow = (uint32_t)(wn * 32 + (lane & 7) + (((lane >> 4) & 1) * 8));
    const uint32_t b_loff = b_lrow * 80 + (((lane >> 3) & 1) * 16);

    float acc[2][4][4];
    #pragma unroll
    for (int mf = 0; mf < 2; mf++)
        #pragma unroll
        for (int nf = 0; nf < 4; nf++)
            #pragma unroll
            for (int i = 0; i < 4; i++) acc[mf][nf][i] = 0.f;

    gemm_stage<KDIM>(tid, row0, col0, 0, 0, Ahp, Alp, Bhp, sb);
    CP_COMMIT();

    for (int kc = 0; kc < NCH; kc++) {
        if (kc + 1 < NCH) {
            gemm_stage<KDIM>(tid, row0, col0, (kc + 1) * 32, (kc + 1) & 1,
                             Ahp, Alp, Bhp, sb);
            CP_COMMIT();
            asm volatile("cp.async.wait_group 1;" ::: "memory");
        } else {
            asm volatile("cp.async.wait_group 0;" ::: "memory");
        }
        __syncthreads();

        const uint32_t base = sb + (kc & 1) * BUF_SZ;

        #pragma unroll
        for (int ks = 0; ks < 2; ks++) {
            const uint32_t kb = ks * 32;           // 16 f16 = 32 bytes
            uint32_t AH[2][4], AL[2][4];
            #pragma unroll
            for (int mf = 0; mf < 2; mf++) {
                uint32_t ad = base + a_loff + mf * (16 * 80) + kb;
                ldm_x4(AH[mf], ad);
                ldm_x4(AL[mf], ad + AL_OFF);
            }
            #pragma unroll
            for (int pnf = 0; pnf < 2; pnf++) {
                uint32_t bd = base + BH_OFF + b_loff + pnf * (16 * 80) + kb;
                uint32_t BH4[4];
                ldm_x4(BH4, bd);
                #pragma unroll
                for (int half = 0; half < 2; half++) {
                    const uint32_t* bh = BH4 + half * 2;
                    float* a0 = acc[0][pnf * 2 + half];
                    float* a1 = acc[1][pnf * 2 + half];
                    mma_f16(a0, AH[0], bh);
                    mma_f16(a0, AL[0], bh);
                    mma_f16(a1, AH[1], bh);
                    mma_f16(a1, AL[1], bh);
                }
            }
        }
        __syncthreads();
    }

    // epilogue: fp32 accumulators -> C
    #pragma unroll
    for (int mf = 0; mf < 2; mf++) {
        int row = row0 + wm * 32 + mf * 16 + g;
        #pragma unroll
        for (int nf = 0; nf < 4; nf++) {
            int col = col0 + wn * 32 + nf * 8 + 2 * tg;
            if (row < N_PTS)
                *(float2*)(C + (size_t)row * HDIM + col) =
                    make_float2(acc[mf][nf][0], acc[mf][nf][1]);
            if (row + 8 < N_PTS)
                *(float2*)(C + (size_t)(row + 8) * HDIM + col) =
                    make_float2(acc[mf][nf][2], acc[mf][nf][3]);
        }
    }
}

// -------- assemble stage 1:  h = relu(b1 + 3 gathered taps) -> fp16 hi/lo --
__global__ __launch_bounds__(256)
void assemble1_kernel(const float* __restrict__ b1) {
    int idx = blockIdx.x * 256 + threadIdx.x;      // N_PTS * 72 float4 tasks
    if (idx >= N_PTS * 72) return;
    int p = idx / 72;
    int gidx = idx - p * 72;
    int c = gidx / 24;          // tap 0..2
    int j = gidx - c * 24;      // float4 within 96
    int prev = g_prev[c * N_PTS + p];
    int next = g_next[c * N_PTS + p];
    float4 v = ((const float4*)b1)[j];
    if (prev >= 0) {
        float4 z = *(const float4*)(g_Z + (size_t)prev * HDIM + j * 4);
        v.x += z.x; v.y += z.y; v.z += z.z; v.w += z.w;
    }
    {
        float4 z = *(const float4*)(g_Z + (size_t)p * HDIM + FDIM + j * 4);
        v.x += z.x; v.y += z.y; v.z += z.z; v.w += z.w;
    }
    if (next >= 0) {
        float4 z = *(const float4*)(g_Z + (size_t)next * HDIM + 2 * FDIM + j * 4);
        v.x += z.x; v.y += z.y; v.z += z.z; v.w += z.w;
    }
    v.x = fmaxf(v.x, 0.f); v.y = fmaxf(v.y, 0.f);
    v.z = fmaxf(v.z, 0.f); v.w = fmaxf(v.w, 0.f);
    uint32_t h0, l0, h1, l1;
    split2(make_float2(v.x, v.y), h0, l0);
    split2(make_float2(v.z, v.w), h1, l1);
    int o = p * 72 + c * 24 + j;                   // uint2 (4-elem) index
    ((uint2*)g_hh)[o] = make_uint2(h0, h1);
    ((uint2*)g_hl)[o] = make_uint2(l0, l1);
}

// ------- assemble stage 2 + residual + layernorm (warp per point) ----------
__global__ __launch_bounds__(256)
void assemble2_ln_kernel(const float* __restrict__ b2,
                         const float* __restrict__ gamma,
                         const float* __restrict__ beta,
                         float* __restrict__ out) {
    int p    = (blockIdx.x * 256 + threadIdx.x) >> 5;   // warp per point
    int lane = threadIdx.x & 31;
    float4 xv[3];
    float s = 0.f, q = 0.f;
    if (lane < 24) {
        #pragma unroll
        for (int c = 0; c < 3; c++) {
            int prev = g_prev[c * N_PTS + p];
            int next = g_next[c * N_PTS + p];
            float4 v = ((const float4*)b2)[lane];
            if (prev >= 0) {
                float4 z = *(const float4*)(g_Zh + (size_t)prev * HDIM + lane * 4);
                v.x += z.x; v.y += z.y; v.z += z.z; v.w += z.w;
            }
            {
                float4 z = *(const float4*)(g_Zh + (size_t)p * HDIM + FDIM + lane * 4);
                v.x += z.x; v.y += z.y; v.z += z.z; v.w += z.w;
            }
            if (next >= 0) {
                float4 z = *(const float4*)(g_Zh + (size_t)next * HDIM + 2 * FDIM + lane * 4);
                v.x += z.x; v.y += z.y; v.z += z.z; v.w += z.w;
            }
            int o = p * 72 + c * 24 + lane;
            uint2 hh = ((const uint2*)g_hh)[o];
            uint2 hl = ((const uint2*)g_hl)[o];
            float2 a0 = up2(hh.x), a1 = up2(hh.y);
            float2 b0 = up2(hl.x), b1 = up2(hl.y);
            float4 x;
            x.x = (a0.x + b0.x) + fmaxf(v.x, 0.f);
            x.y = (a0.y + b0.y) + fmaxf(v.y, 0.f);
            x.z = (a1.x + b1.x) + fmaxf(v.z, 0.f);
            x.w = (a1.y + b1.y) + fmaxf(v.w, 0.f);
            xv[c] = x;
            s += x.x + x.y + x.z + x.w;
            q += x.x * x.x + x.y * x.y + x.z * x.z + x.w * x.w;
        }
    }
    #pragma unroll
    for (int o = 16; o > 0; o >>= 1) {
        s += __shfl_xor_sync(0xffffffffu, s, o);
        q += __shfl_xor_sync(0xffffffffu, q, o);
    }
    float mu  = s * (1.f / HDIM);
    float var = q * (1.f / HDIM) - mu * mu;
    float r   = rsqrtf(var + EPSV);
    if (lane < 24) {
        #pragma unroll
        for (int c = 0; c < 3; c++) {
            float4 gm = ((const float4*)gamma)[c * 24 + lane];
            float4 bt = ((const float4*)beta)[c * 24 + lane];
            float4 x  = xv[c];
            float4 o4;
            o4.x = (x.x - mu) * r * gm.x + bt.x;
            o4.y = (x.y - mu) * r * gm.y + bt.y;
            o4.z = (x.z - mu) * r * gm.z + bt.z;
            o4.w = (x.w - mu) * r * gm.w + bt.w;
            *(float4*)(out + (size_t)p * HDIM + c * FDIM + lane * 4) = o4;
        }
    }
}

// ---------------- index pass-through tail ----------------------------------
__global__ void copy_index_kernel(const int* __restrict__ index,
                                  float* __restrict__ out, int count) {
    int t = blockIdx.x * blockDim.x + threadIdx.x;
    if (t < count) out[t] = (float)index[t];
}

// ---------------------------------------------------------------------------
extern "C" void kernel_launch(void* const* d_in, const int* in_sizes, int n_in,
                              void* d_out, int out_size) {
    const float* X     = (const float*)d_in[0];
    const int*   index = (const int*)  d_in[1];
    const float* W1    = (const float*)d_in[2];
    const float* b1    = (const float*)d_in[3];
    const float* W2    = (const float*)d_in[4];
    const float* b2    = (const float*)d_in[5];
    const float* gamma = (const float*)d_in[6];
    const float* beta  = (const float*)d_in[7];
    float* out = (float*)d_out;

    cudaFuncSetAttribute(mma_gemm_kernel<1>,
                         cudaFuncAttributeMaxDynamicSharedMemorySize, GSM_TOTAL);
    cudaFuncSetAttribute(mma_gemm_kernel<2>,
                         cudaFuncAttributeMaxDynamicSharedMemorySize, GSM_TOTAL);

    split_x_kernel<<<(N_PTS * 24 + 255) / 256, 256>>>(X);
    pack_w_kernel<<<(HDIM * HDIM + 255) / 256, 256>>>(W1, W2);
    prevnext_kernel<<<(NCOLS * N_PTS + 255) / 256, 256>>>(index);

    dim3 gg(N_MTILE, 3);
    mma_gemm_kernel<1><<<gg, NTHR, GSM_TOTAL>>>();        // Z  = X @ B1^T
    assemble1_kernel<<<(N_PTS * 72 + 255) / 256, 256>>>(b1);
    mma_gemm_kernel<2><<<gg, NTHR, GSM_TOTAL>>>();        // Zh = h @ B2^T
    assemble2_ln_kernel<<<(N_PTS * 32 + 255) / 256, 256>>>(b2, gamma, beta, out);

    int tail = out_size - N_PTS * HDIM;
    if (tail > 0) {
        if (tail > NCOLS * N_PTS) tail = NCOLS * N_PTS;
        copy_index_kernel<<<(tail + 255) / 256, 256>>>(
            index, out + (size_t)N_PTS * HDIM, tail);
    }
}

// round 10
// speedup vs baseline: 1.5417x; 1.0054x over previous
#include <cuda_runtime.h>
#include <cuda_fp16.h>
#include <cstdint>

#define N_PTS 200000
#define CDIM 96
#define FDIM 96
#define NCOLS 3
#define HDIM 288          // NCOLS * FDIM
#define EPSV 1e-3f

// ---------------- scratch (device globals: no allocation allowed) ----------
__device__ float g_Z [(size_t)N_PTS * HDIM];   // stage-1 GEMM out
__device__ float g_Zh[(size_t)N_PTS * HDIM];   // stage-2 GEMM out
__device__ int   g_prev[NCOLS * N_PTS];
__device__ int   g_next[NCOLS * N_PTS];
// A operands pre-split to fp16 hi/lo
__device__ __half g_Xh[(size_t)N_PTS * CDIM];
__device__ __half g_Xl[(size_t)N_PTS * CDIM];
__device__ __half g_hh[(size_t)N_PTS * HDIM];
__device__ __half g_hl[(size_t)N_PTS * HDIM];
// fp16 weights (hi only), MMA layout: B[n][k]  (n = tap*FDIM + f)
__device__ __half g_B1h[HDIM * CDIM];
__device__ __half g_B2h[HDIM * HDIM];

// ======================= helpers ==========================================
__device__ __forceinline__ uint32_t smem_u32(const void* p) {
    uint32_t a;
    asm("{ .reg .u64 t; cvta.to.shared.u64 t, %1; cvt.u32.u64 %0, t; }"
        : "=r"(a) : "l"(p));
    return a;
}
// .cg: bypass L1 (keep L1 free for ldmatrix traffic)
__device__ __forceinline__ void cp16(uint32_t dst, const void* src) {
    asm volatile("cp.async.cg.shared.global [%0], [%1], 16;"
                 :: "r"(dst), "l"(src) : "memory");
}
__device__ __forceinline__ void cp16p(uint32_t dst, const void* src, uint32_t sz) {
    asm volatile("cp.async.cg.shared.global [%0], [%1], 16, %2;"
                 :: "r"(dst), "l"(src), "r"(sz) : "memory");
}
#define CP_COMMIT() asm volatile("cp.async.commit_group;" ::: "memory")

__device__ __forceinline__ void ldm_x4(uint32_t* r, uint32_t addr) {
    asm volatile("ldmatrix.sync.aligned.m8n8.x4.shared.b16 {%0,%1,%2,%3}, [%4];"
                 : "=r"(r[0]), "=r"(r[1]), "=r"(r[2]), "=r"(r[3]) : "r"(addr));
}

// D += A*B  (m16n8k16, fp16 in, fp32 acc)
__device__ __forceinline__ void mma_f16(float* d, const uint32_t* a,
                                        const uint32_t* b) {
    asm volatile(
        "mma.sync.aligned.m16n8k16.row.col.f32.f16.f16.f32 "
        "{%0,%1,%2,%3}, {%4,%5,%6,%7}, {%8,%9}, {%0,%1,%2,%3};"
        : "+f"(d[0]), "+f"(d[1]), "+f"(d[2]), "+f"(d[3])
        : "r"(a[0]), "r"(a[1]), "r"(a[2]), "r"(a[3]), "r"(b[0]), "r"(b[1]));
}

// fp32 pair -> f16x2 hi + f16x2 lo (residual)
__device__ __forceinline__ void split2(float2 v, uint32_t& hi, uint32_t& lo) {
    __half2 h = __floats2half2_rn(v.x, v.y);
    float2 hf = __half22float2(h);
    __half2 l = __floats2half2_rn(v.x - hf.x, v.y - hf.y);
    hi = *reinterpret_cast<uint32_t*>(&h);
    lo = *reinterpret_cast<uint32_t*>(&l);
}
// f16x2 word -> float2 (exact)
__device__ __forceinline__ float2 up2(uint32_t u) {
    __half2 h = *reinterpret_cast<__half2*>(&u);
    return __half22float2(h);
}

// ---------------- split X into fp16 hi/lo ----------------------------------
__global__ void split_x_kernel(const float* __restrict__ X) {
    int idx = blockIdx.x * 256 + threadIdx.x;        // groups of 4 floats
    if (idx >= N_PTS * (CDIM / 4)) return;
    float4 v = ((const float4*)X)[idx];
    uint32_t h0, l0, h1, l1;
    split2(make_float2(v.x, v.y), h0, l0);
    split2(make_float2(v.z, v.w), h1, l1);
    ((uint2*)g_Xh)[idx] = make_uint2(h0, h1);
    ((uint2*)g_Xl)[idx] = make_uint2(l0, l1);
}

// ---------------- pack weights: fp16 (hi), [n][k] MMA layout ---------------
__global__ void pack_w_kernel(const float* __restrict__ W1,
                              const float* __restrict__ W2) {
    int t = blockIdx.x * blockDim.x + threadIdx.x;
    if (t < HDIM * HDIM) {                       // W2: (3, 288, 96)
        int n = t / HDIM, k = t % HDIM;
        int tap = n / FDIM, f = n % FDIM;
        g_B2h[(size_t)n * HDIM + k] =
            __float2half_rn(W2[((size_t)tap * HDIM + k) * FDIM + f]);
    }
    if (t < HDIM * CDIM) {                       // W1: (3, 96, 96)
        int n = t / CDIM, k = t % CDIM;
        int tap = n / FDIM, f = n % FDIM;
        g_B1h[(size_t)n * CDIM + k] =
            __float2half_rn(W1[((size_t)tap * CDIM + k) * FDIM + f]);
    }
}

// ---------------- neighbor maps --------------------------------------------
__global__ void prevnext_kernel(const int* __restrict__ index) {
    int t = blockIdx.x * blockDim.x + threadIdx.x;
    if (t >= NCOLS * N_PTS) return;
    int i = t / NCOLS;
    int c = t % NCOLS;
    int p = index[t];
    g_prev[c * N_PTS + p] = (i > 0)         ? index[t - NCOLS] : -1;
    g_next[c * N_PTS + p] = (i < N_PTS - 1) ? index[t + NCOLS] : -1;
}

// ============ split-fp16 HMMA GEMM:  C[M,288] = A[M,K] @ B[288,K]^T ========
// 2-pass: C = (Ah + Al) @ Bh^T   (dropped A@Bl ~ 2^-11 relative)
// CTA: BM=128, BN=96, BK=32. 12 warps 4(M) x 3(N); warp tile 32x32 (32 acc).
// Grid (3, 1563): N-tiles fastest -> the 3 CTAs sharing A rows are adjacent
// in launch order, so A re-reads hit L2 instead of DRAM.
// smem per buf: Ah 128x80B, Al 128x80B, Bh 96x80B = 28160 B.
#define BUF_SZ   28160
#define AL_OFF   10240
#define BH_OFF   20480
#define GSM_TOTAL (2 * BUF_SZ)       // 56320 -> 2 CTAs/SM
#define N_MTILE  1563                // ceil(200000/128)
#define NTHR     384

template <int KDIM>
__device__ __forceinline__ void gemm_stage(
        int tid, int row0, int col0, int k0, int buf,
        const __half* __restrict__ Ahp,
        const __half* __restrict__ Alp,
        const __half* __restrict__ Bhp,
        uint32_t sb) {
    uint32_t base = sb + buf * BUF_SZ;
    // A: 128 rows x 32 k fp16 = 512 x 16B per array
    for (int idx = tid; idx < 512; idx += NTHR) {
        int r = idx >> 2, c = idx & 3;
        int gr = row0 + r;
        uint32_t sz = (gr < N_PTS) ? 16u : 0u;
        size_t go = (size_t)gr * KDIM + k0 + c * 8;
        uint32_t so = (uint32_t)(r * 80 + c * 16);
        cp16p(base + so,          Ahp + go, sz);
        cp16p(base + AL_OFF + so, Alp + go, sz);
    }
    // B: 96 rows x 32 k = 384 x 16B; exactly one per thread
    {
        int r = tid >> 2, c = tid & 3;
        size_t go = (size_t)(col0 + r) * KDIM + k0 + c * 8;
        cp16(base + BH_OFF + (uint32_t)(r * 80 + c * 16), Bhp + go);
    }
}

template <int STAGE>
__global__ __launch_bounds__(NTHR, 2)
void mma_gemm_kernel() {
    constexpr int KDIM = (STAGE == 1) ? CDIM : HDIM;
    constexpr int NCH  = KDIM / 32;
    const __half* __restrict__ Ahp = (STAGE == 1) ? g_Xh : g_hh;
    const __half* __restrict__ Alp = (STAGE == 1) ? g_Xl : g_hl;
    const __half* __restrict__ Bhp = (STAGE == 1) ? g_B1h : g_B2h;
    float* __restrict__ C = (STAGE == 1) ? g_Z : g_Zh;

    extern __shared__ char smem[];
    const uint32_t sb = smem_u32(smem);

    const int tid  = threadIdx.x;
    const int wid  = tid >> 5;
    const int lane = tid & 31;
    const int g    = lane >> 2;        // 0..7
    const int tg   = lane & 3;         // 0..3
    const int wm   = wid & 3;          // M warp 0..3
    const int wn   = wid >> 2;         // N warp 0..2
    const int row0 = blockIdx.y * 128; // M tile (slow grid dim)
    const int col0 = blockIdx.x * 96;  // N tile (fast grid dim -> L2 reuse)

    // ldmatrix lane addressing (byte offsets within a buffer)
    const uint32_t a_lrow = (uint32_t)(wm * 32 + (lane & 15));
    const uint32_t a_loff = a_lrow * 80 + ((lane >> 4) * 16);
    const uint32_t b_lrow = (uint32_t)(wn * 32 + (lane & 7) + (((lane >> 4) & 1) * 8));
    const uint32_t b_loff = b_lrow * 80 + (((lane >> 3) & 1) * 16);

    float acc[2][4][4];
    #pragma unroll
    for (int mf = 0; mf < 2; mf++)
        #pragma unroll
        for (int nf = 0; nf < 4; nf++)
            #pragma unroll
            for (int i = 0; i < 4; i++) acc[mf][nf][i] = 0.f;

    gemm_stage<KDIM>(tid, row0, col0, 0, 0, Ahp, Alp, Bhp, sb);
    CP_COMMIT();

    for (int kc = 0; kc < NCH; kc++) {
        if (kc + 1 < NCH) {
            gemm_stage<KDIM>(tid, row0, col0, (kc + 1) * 32, (kc + 1) & 1,
                             Ahp, Alp, Bhp, sb);
            CP_COMMIT();
            asm volatile("cp.async.wait_group 1;" ::: "memory");
        } else {
            asm volatile("cp.async.wait_group 0;" ::: "memory");
        }
        __syncthreads();

        const uint32_t base = sb + (kc & 1) * BUF_SZ;

        #pragma unroll
        for (int ks = 0; ks < 2; ks++) {
            const uint32_t kb = ks * 32;           // 16 f16 = 32 bytes
            uint32_t AH[2][4], AL[2][4];
            #pragma unroll
            for (int mf = 0; mf < 2; mf++) {
                uint32_t ad = base + a_loff + mf * (16 * 80) + kb;
                ldm_x4(AH[mf], ad);
                ldm_x4(AL[mf], ad + AL_OFF);
            }
            #pragma unroll
            for (int pnf = 0; pnf < 2; pnf++) {
                uint32_t bd = base + BH_OFF + b_loff + pnf * (16 * 80) + kb;
                uint32_t BH4[4];
                ldm_x4(BH4, bd);
                #pragma unroll
                for (int half = 0; half < 2; half++) {
                    const uint32_t* bh = BH4 + half * 2;
                    float* a0 = acc[0][pnf * 2 + half];
                    float* a1 = acc[1][pnf * 2 + half];
                    mma_f16(a0, AH[0], bh);
                    mma_f16(a0, AL[0], bh);
                    mma_f16(a1, AH[1], bh);
                    mma_f16(a1, AL[1], bh);
                }
            }
        }
        __syncthreads();
    }

    // epilogue: fp32 accumulators -> C
    #pragma unroll
    for (int mf = 0; mf < 2; mf++) {
        int row = row0 + wm * 32 + mf * 16 + g;
        #pragma unroll
        for (int nf = 0; nf < 4; nf++) {
            int col = col0 + wn * 32 + nf * 8 + 2 * tg;
            if (row < N_PTS)
                *(float2*)(C + (size_t)row * HDIM + col) =
                    make_float2(acc[mf][nf][0], acc[mf][nf][1]);
            if (row + 8 < N_PTS)
                *(float2*)(C + (size_t)(row + 8) * HDIM + col) =
                    make_float2(acc[mf][nf][2], acc[mf][nf][3]);
        }
    }
}

// -------- assemble stage 1:  h = relu(b1 + 3 gathered taps) -> fp16 hi/lo --
__global__ __launch_bounds__(256)
void assemble1_kernel(const float* __restrict__ b1) {
    int idx = blockIdx.x * 256 + threadIdx.x;      // N_PTS * 72 float4 tasks
    if (idx >= N_PTS * 72) return;
    int p = idx / 72;
    int gidx = idx - p * 72;
    int c = gidx / 24;          // tap 0..2
    int j = gidx - c * 24;      // float4 within 96
    int prev = g_prev[c * N_PTS + p];
    int next = g_next[c * N_PTS + p];
    float4 v = ((const float4*)b1)[j];
    if (prev >= 0) {
        float4 z = *(const float4*)(g_Z + (size_t)prev * HDIM + j * 4);
        v.x += z.x; v.y += z.y; v.z += z.z; v.w += z.w;
    }
    {
        float4 z = *(const float4*)(g_Z + (size_t)p * HDIM + FDIM + j * 4);
        v.x += z.x; v.y += z.y; v.z += z.z; v.w += z.w;
    }
    if (next >= 0) {
        float4 z = *(const float4*)(g_Z + (size_t)next * HDIM + 2 * FDIM + j * 4);
        v.x += z.x; v.y += z.y; v.z += z.z; v.w += z.w;
    }
    v.x = fmaxf(v.x, 0.f); v.y = fmaxf(v.y, 0.f);
    v.z = fmaxf(v.z, 0.f); v.w = fmaxf(v.w, 0.f);
    uint32_t h0, l0, h1, l1;
    split2(make_float2(v.x, v.y), h0, l0);
    split2(make_float2(v.z, v.w), h1, l1);
    int o = p * 72 + c * 24 + j;                   // uint2 (4-elem) index
    ((uint2*)g_hh)[o] = make_uint2(h0, h1);
    ((uint2*)g_hl)[o] = make_uint2(l0, l1);
}

// ------- assemble stage 2 + residual + layernorm (warp per point) ----------
__global__ __launch_bounds__(256)
void assemble2_ln_kernel(const float* __restrict__ b2,
                         const float* __restrict__ gamma,
                         const float* __restrict__ beta,
                         float* __restrict__ out) {
    int p    = (blockIdx.x * 256 + threadIdx.x) >> 5;   // warp per point
    int lane = threadIdx.x & 31;
    float4 xv[3];
    float s = 0.f, q = 0.f;
    if (lane < 24) {
        #pragma unroll
        for (int c = 0; c < 3; c++) {
            int prev = g_prev[c * N_PTS + p];
            int next = g_next[c * N_PTS + p];
            float4 v = ((const float4*)b2)[lane];
            if (prev >= 0) {
                float4 z = *(const float4*)(g_Zh + (size_t)prev * HDIM + lane * 4);
                v.x += z.x; v.y += z.y; v.z += z.z; v.w += z.w;
            }
            {
                float4 z = *(const float4*)(g_Zh + (size_t)p * HDIM + FDIM + lane * 4);
                v.x += z.x; v.y += z.y; v.z += z.z; v.w += z.w;
            }
            if (next >= 0) {
                float4 z = *(const float4*)(g_Zh + (size_t)next * HDIM + 2 * FDIM + lane * 4);
                v.x += z.x; v.y += z.y; v.z += z.z; v.w += z.w;
            }
            int o = p * 72 + c * 24 + lane;
            uint2 hh = ((const uint2*)g_hh)[o];
            uint2 hl = ((const uint2*)g_hl)[o];
            float2 a0 = up2(hh.x), a1 = up2(hh.y);
            float2 b0 = up2(hl.x), b1 = up2(hl.y);
            float4 x;
            x.x = (a0.x + b0.x) + fmaxf(v.x, 0.f);
            x.y = (a0.y + b0.y) + fmaxf(v.y, 0.f);
            x.z = (a1.x + b1.x) + fmaxf(v.z, 0.f);
            x.w = (a1.y + b1.y) + fmaxf(v.w, 0.f);
            xv[c] = x;
            s += x.x + x.y + x.z + x.w;
            q += x.x * x.x + x.y * x.y + x.z * x.z + x.w * x.w;
        }
    }
    #pragma unroll
    for (int o = 16; o > 0; o >>= 1) {
        s += __shfl_xor_sync(0xffffffffu, s, o);
        q += __shfl_xor_sync(0xffffffffu, q, o);
    }
    float mu  = s * (1.f / HDIM);
    float var = q * (1.f / HDIM) - mu * mu;
    float r   = rsqrtf(var + EPSV);
    if (lane < 24) {
        #pragma unroll
        for (int c = 0; c < 3; c++) {
            float4 gm = ((const float4*)gamma)[c * 24 + lane];
            float4 bt = ((const float4*)beta)[c * 24 + lane];
            float4 x  = xv[c];
            float4 o4;
            o4.x = (x.x - mu) * r * gm.x + bt.x;
            o4.y = (x.y - mu) * r * gm.y + bt.y;
            o4.z = (x.z - mu) * r * gm.z + bt.z;
            o4.w = (x.w - mu) * r * gm.w + bt.w;
            *(float4*)(out + (size_t)p * HDIM + c * FDIM + lane * 4) = o4;
        }
    }
}

// ---------------- index pass-through tail ----------------------------------
__global__ void copy_index_kernel(const int* __restrict__ index,
                                  float* __restrict__ out, int count) {
    int t = blockIdx.x * blockDim.x + threadIdx.x;
    if (t < count) out[t] = (float)index[t];
}

// ---------------------------------------------------------------------------
extern "C" void kernel_launch(void* const* d_in, const int* in_sizes, int n_in,
                              void* d_out, int out_size) {
    const float* X     = (const float*)d_in[0];
    const int*   index = (const int*)  d_in[1];
    const float* W1    = (const float*)d_in[2];
    const float* b1    = (const float*)d_in[3];
    const float* W2    = (const float*)d_in[4];
    const float* b2    = (const float*)d_in[5];
    const float* gamma = (const float*)d_in[6];
    const float* beta  = (const float*)d_in[7];
    float* out = (float*)d_out;

    cudaFuncSetAttribute(mma_gemm_kernel<1>,
                         cudaFuncAttributeMaxDynamicSharedMemorySize, GSM_TOTAL);
    cudaFuncSetAttribute(mma_gemm_kernel<2>,
                         cudaFuncAttributeMaxDynamicSharedMemorySize, GSM_TOTAL);

    split_x_kernel<<<(N_PTS * 24 + 255) / 256, 256>>>(X);
    pack_w_kernel<<<(HDIM * HDIM + 255) / 256, 256>>>(W1, W2);
    prevnext_kernel<<<(NCOLS * N_PTS + 255) / 256, 256>>>(index);

    dim3 gg(3, N_MTILE);                          // N fastest -> A L2 reuse
    mma_gemm_kernel<1><<<gg, NTHR, GSM_TOTAL>>>();        // Z  = X @ B1^T
    assemble1_kernel<<<(N_PTS * 72 + 255) / 256, 256>>>(b1);
    mma_gemm_kernel<2><<<gg, NTHR, GSM_TOTAL>>>();        // Zh = h @ B2^T
    assemble2_ln_kernel<<<(N_PTS * 32 + 255) / 256, 256>>>(b2, gamma, beta, out);

    int tail = out_size - N_PTS * HDIM;
    if (tail > 0) {
        if (tail > NCOLS * N_PTS) tail = NCOLS * N_PTS;
        copy_index_kernel<<<(tail + 255) / 256, 256>>>(
            index, out + (size_t)N_PTS * HDIM, tail);
    }
}

// round 11
// speedup vs baseline: 1.7301x; 1.1222x over previous
#include <cuda_runtime.h>
#include <cuda_fp16.h>
#include <cstdint>

#define N_PTS 200000
#define CDIM 96
#define FDIM 96
#define NCOLS 3
#define HDIM 288          // NCOLS * FDIM
#define EPSV 1e-3f

// ---------------- scratch (device globals: no allocation allowed) ----------
__device__ float g_Z [(size_t)N_PTS * HDIM];   // stage-1 GEMM out
__device__ float g_Zh[(size_t)N_PTS * HDIM];   // stage-2 GEMM out
__device__ int   g_prev[NCOLS * N_PTS];
__device__ int   g_next[NCOLS * N_PTS];
// A operands pre-split to fp16 hi/lo
__device__ __half g_Xh[(size_t)N_PTS * CDIM];
__device__ __half g_Xl[(size_t)N_PTS * CDIM];
__device__ __half g_hh[(size_t)N_PTS * HDIM];
__device__ __half g_hl[(size_t)N_PTS * HDIM];
// fp16 weights (hi only), MMA layout: B[n][k]  (n = tap*FDIM + f)
__device__ __half g_B1h[HDIM * CDIM];
__device__ __half g_B2h[HDIM * HDIM];

// ======================= helpers ==========================================
__device__ __forceinline__ uint32_t smem_u32(const void* p) {
    uint32_t a;
    asm("{ .reg .u64 t; cvta.to.shared.u64 t, %1; cvt.u32.u64 %0, t; }"
        : "=r"(a) : "l"(p));
    return a;
}
// .cg: bypass L1 (keep L1 free for ldmatrix traffic)
__device__ __forceinline__ void cp16(uint32_t dst, const void* src) {
    asm volatile("cp.async.cg.shared.global [%0], [%1], 16;"
                 :: "r"(dst), "l"(src) : "memory");
}
__device__ __forceinline__ void cp16p(uint32_t dst, const void* src, uint32_t sz) {
    asm volatile("cp.async.cg.shared.global [%0], [%1], 16, %2;"
                 :: "r"(dst), "l"(src), "r"(sz) : "memory");
}
#define CP_COMMIT() asm volatile("cp.async.commit_group;" ::: "memory")

__device__ __forceinline__ void ldm_x4(uint32_t* r, uint32_t addr) {
    asm volatile("ldmatrix.sync.aligned.m8n8.x4.shared.b16 {%0,%1,%2,%3}, [%4];"
                 : "=r"(r[0]), "=r"(r[1]), "=r"(r[2]), "=r"(r[3]) : "r"(addr));
}

// D += A*B  (m16n8k16, fp16 in, fp32 acc)
__device__ __forceinline__ void mma_f16(float* d, const uint32_t* a,
                                        const uint32_t* b) {
    asm volatile(
        "mma.sync.aligned.m16n8k16.row.col.f32.f16.f16.f32 "
        "{%0,%1,%2,%3}, {%4,%5,%6,%7}, {%8,%9}, {%0,%1,%2,%3};"
        : "+f"(d[0]), "+f"(d[1]), "+f"(d[2]), "+f"(d[3])
        : "r"(a[0]), "r"(a[1]), "r"(a[2]), "r"(a[3]), "r"(b[0]), "r"(b[1]));
}

// fp32 pair -> f16x2 hi + f16x2 lo (residual)
__device__ __forceinline__ void split2(float2 v, uint32_t& hi, uint32_t& lo) {
    __half2 h = __floats2half2_rn(v.x, v.y);
    float2 hf = __half22float2(h);
    __half2 l = __floats2half2_rn(v.x - hf.x, v.y - hf.y);
    hi = *reinterpret_cast<uint32_t*>(&h);
    lo = *reinterpret_cast<uint32_t*>(&l);
}
// f16x2 word -> float2 (exact)
__device__ __forceinline__ float2 up2(uint32_t u) {
    __half2 h = *reinterpret_cast<__half2*>(&u);
    return __half22float2(h);
}

// ---------------- split X into fp16 hi/lo ----------------------------------
__global__ void split_x_kernel(const float* __restrict__ X) {
    int idx = blockIdx.x * 256 + threadIdx.x;        // groups of 4 floats
    if (idx >= N_PTS * (CDIM / 4)) return;
    float4 v = ((const float4*)X)[idx];
    uint32_t h0, l0, h1, l1;
    split2(make_float2(v.x, v.y), h0, l0);
    split2(make_float2(v.z, v.w), h1, l1);
    ((uint2*)g_Xh)[idx] = make_uint2(h0, h1);
    ((uint2*)g_Xl)[idx] = make_uint2(l0, l1);
}

// ---------------- pack weights: fp16 (hi), [n][k] MMA layout ---------------
__global__ void pack_w_kernel(const float* __restrict__ W1,
                              const float* __restrict__ W2) {
    int t = blockIdx.x * blockDim.x + threadIdx.x;
    if (t < HDIM * HDIM) {                       // W2: (3, 288, 96)
        int n = t / HDIM, k = t % HDIM;
        int tap = n / FDIM, f = n % FDIM;
        g_B2h[(size_t)n * HDIM + k] =
            __float2half_rn(W2[((size_t)tap * HDIM + k) * FDIM + f]);
    }
    if (t < HDIM * CDIM) {                       // W1: (3, 96, 96)
        int n = t / CDIM, k = t % CDIM;
        int tap = n / FDIM, f = n % FDIM;
        g_B1h[(size_t)n * CDIM + k] =
            __float2half_rn(W1[((size_t)tap * CDIM + k) * FDIM + f]);
    }
}

// ---------------- neighbor maps --------------------------------------------
__global__ void prevnext_kernel(const int* __restrict__ index) {
    int t = blockIdx.x * blockDim.x + threadIdx.x;
    if (t >= NCOLS * N_PTS) return;
    int i = t / NCOLS;
    int c = t % NCOLS;
    int p = index[t];
    g_prev[c * N_PTS + p] = (i > 0)         ? index[t - NCOLS] : -1;
    g_next[c * N_PTS + p] = (i < N_PTS - 1) ? index[t + NCOLS] : -1;
}

// ============ split-fp16 HMMA GEMM:  C[M,288] = A[M,K] @ B[288,K]^T ========
// STAGE 1 (K=96):  2-pass  C = (Ah + Al) @ Bh^T, 2-stage pipeline
// STAGE 2 (K=288): 1-pass  C = Ah @ Bh^T        , 3-stage pipeline
// CTA: BM=128, BN=96, BK=32. 12 warps 4(M) x 3(N); warp tile 32x32.
// Grid (3, 1563): N-tiles fastest -> A re-reads hit L2.
#define N_MTILE  1563                // ceil(200000/128)
#define NTHR     384
#define ABYTES   10240               // 128 rows x 80B

template <int NPASS, int BUF, int KDIM>
__device__ __forceinline__ void gemm_stage(
        int tid, int row0, int col0, int k0, int buf,
        const __half* __restrict__ Ahp,
        const __half* __restrict__ Alp,
        const __half* __restrict__ Bhp,
        uint32_t sb) {
    uint32_t base = sb + buf * BUF;
    // A: 128 rows x 32 k fp16 = 512 x 16B per array
    for (int idx = tid; idx < 512; idx += NTHR) {
        int r = idx >> 2, c = idx & 3;
        int gr = row0 + r;
        uint32_t sz = (gr < N_PTS) ? 16u : 0u;
        size_t go = (size_t)gr * KDIM + k0 + c * 8;
        uint32_t so = (uint32_t)(r * 80 + c * 16);
        cp16p(base + so, Ahp + go, sz);
        if constexpr (NPASS == 2) cp16p(base + ABYTES + so, Alp + go, sz);
    }
    // B: 96 rows x 32 k = 384 x 16B; exactly one per thread
    {
        int r = tid >> 2, c = tid & 3;
        size_t go = (size_t)(col0 + r) * KDIM + k0 + c * 8;
        cp16(base + NPASS * ABYTES + (uint32_t)(r * 80 + c * 16), Bhp + go);
    }
}

template <int STAGE>
__global__ __launch_bounds__(NTHR, 2)
void mma_gemm_kernel() {
    constexpr int KDIM   = (STAGE == 1) ? CDIM : HDIM;
    constexpr int NCH    = KDIM / 32;
    constexpr int NPASS  = (STAGE == 1) ? 2 : 1;
    constexpr int NSTAGE = (STAGE == 1) ? 2 : 3;
    constexpr int BOFF   = NPASS * ABYTES;
    constexpr int BUF    = BOFF + 7680;
    const __half* __restrict__ Ahp = (STAGE == 1) ? g_Xh : g_hh;
    const __half* __restrict__ Alp = (STAGE == 1) ? g_Xl : g_hl;
    const __half* __restrict__ Bhp = (STAGE == 1) ? g_B1h : g_B2h;
    float* __restrict__ C = (STAGE == 1) ? g_Z : g_Zh;

    extern __shared__ char smem[];
    const uint32_t sb = smem_u32(smem);

    const int tid  = threadIdx.x;
    const int wid  = tid >> 5;
    const int lane = tid & 31;
    const int g    = lane >> 2;        // 0..7
    const int tg   = lane & 3;         // 0..3
    const int wm   = wid & 3;          // M warp 0..3
    const int wn   = wid >> 2;         // N warp 0..2
    const int row0 = blockIdx.y * 128; // M tile (slow grid dim)
    const int col0 = blockIdx.x * 96;  // N tile (fast grid dim -> L2 reuse)

    // ldmatrix lane addressing (byte offsets within a buffer)
    const uint32_t a_lrow = (uint32_t)(wm * 32 + (lane & 15));
    const uint32_t a_loff = a_lrow * 80 + ((lane >> 4) * 16);
    const uint32_t b_lrow = (uint32_t)(wn * 32 + (lane & 7) + (((lane >> 4) & 1) * 8));
    const uint32_t b_loff = b_lrow * 80 + (((lane >> 3) & 1) * 16);

    float acc[2][4][4];
    #pragma unroll
    for (int mf = 0; mf < 2; mf++)
        #pragma unroll
        for (int nf = 0; nf < 4; nf++)
            #pragma unroll
            for (int i = 0; i < 4; i++) acc[mf][nf][i] = 0.f;

    #pragma unroll
    for (int s = 0; s < NSTAGE - 1; s++) {
        gemm_stage<NPASS, BUF, KDIM>(tid, row0, col0, s * 32, s,
                                     Ahp, Alp, Bhp, sb);
        CP_COMMIT();
    }

    for (int kc = 0; kc < NCH; kc++) {
        if (kc + NSTAGE - 1 < NCH) {
            gemm_stage<NPASS, BUF, KDIM>(tid, row0, col0,
                                         (kc + NSTAGE - 1) * 32,
                                         (kc + NSTAGE - 1) % NSTAGE,
                                         Ahp, Alp, Bhp, sb);
            CP_COMMIT();
            asm volatile("cp.async.wait_group %0;" :: "n"(NSTAGE - 1) : "memory");
        } else if (kc + 1 < NCH) {
            asm volatile("cp.async.wait_group 1;" ::: "memory");
        } else {
            asm volatile("cp.async.wait_group 0;" ::: "memory");
        }
        __syncthreads();

        const uint32_t base = sb + (kc % NSTAGE) * BUF;

        #pragma unroll
        for (int ks = 0; ks < 2; ks++) {
            const uint32_t kb = ks * 32;           // 16 f16 = 32 bytes
            uint32_t AH[2][4], AL[2][4];
            #pragma unroll
            for (int mf = 0; mf < 2; mf++) {
                uint32_t ad = base + a_loff + mf * (16 * 80) + kb;
                ldm_x4(AH[mf], ad);
                if constexpr (NPASS == 2) ldm_x4(AL[mf], ad + ABYTES);
            }
            #pragma unroll
            for (int pnf = 0; pnf < 2; pnf++) {
                uint32_t bd = base + BOFF + b_loff + pnf * (16 * 80) + kb;
                uint32_t BH4[4];
                ldm_x4(BH4, bd);
                #pragma unroll
                for (int half = 0; half < 2; half++) {
                    const uint32_t* bh = BH4 + half * 2;
                    float* a0 = acc[0][pnf * 2 + half];
                    float* a1 = acc[1][pnf * 2 + half];
                    mma_f16(a0, AH[0], bh);
                    if constexpr (NPASS == 2) mma_f16(a0, AL[0], bh);
                    mma_f16(a1, AH[1], bh);
                    if constexpr (NPASS == 2) mma_f16(a1, AL[1], bh);
                }
            }
        }
        __syncthreads();
    }

    // epilogue: fp32 accumulators -> C
    #pragma unroll
    for (int mf = 0; mf < 2; mf++) {
        int row = row0 + wm * 32 + mf * 16 + g;
        #pragma unroll
        for (int nf = 0; nf < 4; nf++) {
            int col = col0 + wn * 32 + nf * 8 + 2 * tg;
            if (row < N_PTS)
                *(float2*)(C + (size_t)row * HDIM + col) =
                    make_float2(acc[mf][nf][0], acc[mf][nf][1]);
            if (row + 8 < N_PTS)
                *(float2*)(C + (size_t)(row + 8) * HDIM + col) =
                    make_float2(acc[mf][nf][2], acc[mf][nf][3]);
        }
    }
}

#define GSM1 (2 * (2 * ABYTES + 7680))   // 56320
#define GSM2 (3 * (1 * ABYTES + 7680))   // 53760

// -------- assemble stage 1:  h = relu(b1 + 3 gathered taps) -> fp16 hi/lo --
__global__ __launch_bounds__(256)
void assemble1_kernel(const float* __restrict__ b1) {
    int idx = blockIdx.x * 256 + threadIdx.x;      // N_PTS * 72 float4 tasks
    if (idx >= N_PTS * 72) return;
    int p = idx / 72;
    int gidx = idx - p * 72;
    int c = gidx / 24;          // tap 0..2
    int j = gidx - c * 24;      // float4 within 96
    int prev = g_prev[c * N_PTS + p];
    int next = g_next[c * N_PTS + p];
    float4 v = ((const float4*)b1)[j];
    if (prev >= 0) {
        float4 z = *(const float4*)(g_Z + (size_t)prev * HDIM + j * 4);
        v.x += z.x; v.y += z.y; v.z += z.z; v.w += z.w;
    }
    {
        float4 z = *(const float4*)(g_Z + (size_t)p * HDIM + FDIM + j * 4);
        v.x += z.x; v.y += z.y; v.z += z.z; v.w += z.w;
    }
    if (next >= 0) {
        float4 z = *(const float4*)(g_Z + (size_t)next * HDIM + 2 * FDIM + j * 4);
        v.x += z.x; v.y += z.y; v.z += z.z; v.w += z.w;
    }
    v.x = fmaxf(v.x, 0.f); v.y = fmaxf(v.y, 0.f);
    v.z = fmaxf(v.z, 0.f); v.w = fmaxf(v.w, 0.f);
    uint32_t h0, l0, h1, l1;
    split2(make_float2(v.x, v.y), h0, l0);
    split2(make_float2(v.z, v.w), h1, l1);
    int o = p * 72 + c * 24 + j;                   // uint2 (4-elem) index
    ((uint2*)g_hh)[o] = make_uint2(h0, h1);
    ((uint2*)g_hl)[o] = make_uint2(l0, l1);
}

// ------- assemble stage 2 + residual + layernorm (warp per point) ----------
__global__ __launch_bounds__(256)
void assemble2_ln_kernel(const float* __restrict__ b2,
                         const float* __restrict__ gamma,
                         const float* __restrict__ beta,
                         float* __restrict__ out) {
    int p    = (blockIdx.x * 256 + threadIdx.x) >> 5;   // warp per point
    int lane = threadIdx.x & 31;
    float4 xv[3];
    float s = 0.f, q = 0.f;
    if (lane < 24) {
        #pragma unroll
        for (int c = 0; c < 3; c++) {
            int prev = g_prev[c * N_PTS + p];
            int next = g_next[c * N_PTS + p];
            float4 v = ((const float4*)b2)[lane];
            if (prev >= 0) {
                float4 z = *(const float4*)(g_Zh + (size_t)prev * HDIM + lane * 4);
                v.x += z.x; v.y += z.y; v.z += z.z; v.w += z.w;
            }
            {
                float4 z = *(const float4*)(g_Zh + (size_t)p * HDIM + FDIM + lane * 4);
                v.x += z.x; v.y += z.y; v.z += z.z; v.w += z.w;
            }
            if (next >= 0) {
                float4 z = *(const float4*)(g_Zh + (size_t)next * HDIM + 2 * FDIM + lane * 4);
                v.x += z.x; v.y += z.y; v.z += z.z; v.w += z.w;
            }
            int o = p * 72 + c * 24 + lane;
            uint2 hh = ((const uint2*)g_hh)[o];
            uint2 hl = ((const uint2*)g_hl)[o];
            float2 a0 = up2(hh.x), a1 = up2(hh.y);
            float2 b0 = up2(hl.x), b1 = up2(hl.y);
            float4 x;
            x.x = (a0.x + b0.x) + fmaxf(v.x, 0.f);
            x.y = (a0.y + b0.y) + fmaxf(v.y, 0.f);
            x.z = (a1.x + b1.x) + fmaxf(v.z, 0.f);
            x.w = (a1.y + b1.y) + fmaxf(v.w, 0.f);
            xv[c] = x;
            s += x.x + x.y + x.z + x.w;
            q += x.x * x.x + x.y * x.y + x.z * x.z + x.w * x.w;
        }
    }
    #pragma unroll
    for (int o = 16; o > 0; o >>= 1) {
        s += __shfl_xor_sync(0xffffffffu, s, o);
        q += __shfl_xor_sync(0xffffffffu, q, o);
    }
    float mu  = s * (1.f / HDIM);
    float var = q * (1.f / HDIM) - mu * mu;
    float r   = rsqrtf(var + EPSV);
    if (lane < 24) {
        #pragma unroll
        for (int c = 0; c < 3; c++) {
            float4 gm = ((const float4*)gamma)[c * 24 + lane];
            float4 bt = ((const float4*)beta)[c * 24 + lane];
            float4 x  = xv[c];
            float4 o4;
            o4.x = (x.x - mu) * r * gm.x + bt.x;
            o4.y = (x.y - mu) * r * gm.y + bt.y;
            o4.z = (x.z - mu) * r * gm.z + bt.z;
            o4.w = (x.w - mu) * r * gm.w + bt.w;
            *(float4*)(out + (size_t)p * HDIM + c * FDIM + lane * 4) = o4;
        }
    }
}

// ---------------- index pass-through tail ----------------------------------
__global__ void copy_index_kernel(const int* __restrict__ index,
                                  float* __restrict__ out, int count) {
    int t = blockIdx.x * blockDim.x + threadIdx.x;
    if (t < count) out[t] = (float)index[t];
}

// ---------------------------------------------------------------------------
extern "C" void kernel_launch(void* const* d_in, const int* in_sizes, int n_in,
                              void* d_out, int out_size) {
    const float* X     = (const float*)d_in[0];
    const int*   index = (const int*)  d_in[1];
    const float* W1    = (const float*)d_in[2];
    const float* b1    = (const float*)d_in[3];
    const float* W2    = (const float*)d_in[4];
    const float* b2    = (const float*)d_in[5];
    const float* gamma = (const float*)d_in[6];
    const float* beta  = (const float*)d_in[7];
    float* out = (float*)d_out;

    cudaFuncSetAttribute(mma_gemm_kernel<1>,
                         cudaFuncAttributeMaxDynamicSharedMemorySize, GSM1);
    cudaFuncSetAttribute(mma_gemm_kernel<2>,
                         cudaFuncAttributeMaxDynamicSharedMemorySize, GSM2);

    split_x_kernel<<<(N_PTS * 24 + 255) / 256, 256>>>(X);
    pack_w_kernel<<<(HDIM * HDIM + 255) / 256, 256>>>(W1, W2);
    prevnext_kernel<<<(NCOLS * N_PTS + 255) / 256, 256>>>(index);

    dim3 gg(3, N_MTILE);                          // N fastest -> A L2 reuse
    mma_gemm_kernel<1><<<gg, NTHR, GSM1>>>();        // Z  = X @ B1^T (2-pass)
    assemble1_kernel<<<(N_PTS * 72 + 255) / 256, 256>>>(b1);
    mma_gemm_kernel<2><<<gg, NTHR, GSM2>>>();        // Zh = hh @ B2^T (1-pass)
    assemble2_ln_kernel<<<(N_PTS * 32 + 255) / 256, 256>>>(b2, gamma, beta, out);

    int tail = out_size - N_PTS * HDIM;
    if (tail > 0) {
        if (tail > NCOLS * N_PTS) tail = NCOLS * N_PTS;
        copy_index_kernel<<<(tail + 255) / 256, 256>>>(
            index, out + (size_t)N_PTS * HDIM, tail);
    }
}

// round 12
// speedup vs baseline: 1.9517x; 1.1280x over previous
#include <cuda_runtime.h>
#include <cuda_fp16.h>
#include <cstdint>

#define N_PTS 200000
#define CDIM 96
#define FDIM 96
#define NCOLS 3
#define HDIM 288          // NCOLS * FDIM
#define EPSV 1e-3f

// ---------------- scratch (device globals: no allocation allowed) ----------
__device__ float g_Z [(size_t)N_PTS * HDIM];   // stage-1 GEMM out
__device__ float g_Zh[(size_t)N_PTS * HDIM];   // stage-2 GEMM out
__device__ int   g_prev[NCOLS * N_PTS];
__device__ int   g_next[NCOLS * N_PTS];
// A operands in fp16 (hi only — dropped low terms are ~2^-11 relative)
__device__ __half g_Xh[(size_t)N_PTS * CDIM];
__device__ __half g_hh[(size_t)N_PTS * HDIM];
// fp16 weights (hi only), MMA layout: B[n][k]  (n = tap*FDIM + f)
__device__ __half g_B1h[HDIM * CDIM];
__device__ __half g_B2h[HDIM * HDIM];

// ======================= helpers ==========================================
__device__ __forceinline__ uint32_t smem_u32(const void* p) {
    uint32_t a;
    asm("{ .reg .u64 t; cvta.to.shared.u64 t, %1; cvt.u32.u64 %0, t; }"
        : "=r"(a) : "l"(p));
    return a;
}
// .cg: bypass L1 (keep L1 free for ldmatrix traffic)
__device__ __forceinline__ void cp16(uint32_t dst, const void* src) {
    asm volatile("cp.async.cg.shared.global [%0], [%1], 16;"
                 :: "r"(dst), "l"(src) : "memory");
}
__device__ __forceinline__ void cp16p(uint32_t dst, const void* src, uint32_t sz) {
    asm volatile("cp.async.cg.shared.global [%0], [%1], 16, %2;"
                 :: "r"(dst), "l"(src), "r"(sz) : "memory");
}
#define CP_COMMIT() asm volatile("cp.async.commit_group;" ::: "memory")

__device__ __forceinline__ void ldm_x4(uint32_t* r, uint32_t addr) {
    asm volatile("ldmatrix.sync.aligned.m8n8.x4.shared.b16 {%0,%1,%2,%3}, [%4];"
                 : "=r"(r[0]), "=r"(r[1]), "=r"(r[2]), "=r"(r[3]) : "r"(addr));
}

// D += A*B  (m16n8k16, fp16 in, fp32 acc)
__device__ __forceinline__ void mma_f16(float* d, const uint32_t* a,
                                        const uint32_t* b) {
    asm volatile(
        "mma.sync.aligned.m16n8k16.row.col.f32.f16.f16.f32 "
        "{%0,%1,%2,%3}, {%4,%5,%6,%7}, {%8,%9}, {%0,%1,%2,%3};"
        : "+f"(d[0]), "+f"(d[1]), "+f"(d[2]), "+f"(d[3])
        : "r"(a[0]), "r"(a[1]), "r"(a[2]), "r"(a[3]), "r"(b[0]), "r"(b[1]));
}

// f16x2 word -> float2 (exact)
__device__ __forceinline__ float2 up2(uint32_t u) {
    __half2 h = *reinterpret_cast<__half2*>(&u);
    return __half22float2(h);
}

// ---------------- convert X to fp16 -----------------------------------------
__global__ void split_x_kernel(const float* __restrict__ X) {
    int idx = blockIdx.x * 256 + threadIdx.x;        // groups of 4 floats
    if (idx >= N_PTS * (CDIM / 4)) return;
    float4 v = ((const float4*)X)[idx];
    __half2 h0 = __floats2half2_rn(v.x, v.y);
    __half2 h1 = __floats2half2_rn(v.z, v.w);
    ((uint2*)g_Xh)[idx] = make_uint2(*(uint32_t*)&h0, *(uint32_t*)&h1);
}

// ---------------- pack weights: fp16 (hi), [n][k] MMA layout ---------------
__global__ void pack_w_kernel(const float* __restrict__ W1,
                              const float* __restrict__ W2) {
    int t = blockIdx.x * blockDim.x + threadIdx.x;
    if (t < HDIM * HDIM) {                       // W2: (3, 288, 96)
        int n = t / HDIM, k = t % HDIM;
        int tap = n / FDIM, f = n % FDIM;
        g_B2h[(size_t)n * HDIM + k] =
            __float2half_rn(W2[((size_t)tap * HDIM + k) * FDIM + f]);
    }
    if (t < HDIM * CDIM) {                       // W1: (3, 96, 96)
        int n = t / CDIM, k = t % CDIM;
        int tap = n / FDIM, f = n % FDIM;
        g_B1h[(size_t)n * CDIM + k] =
            __float2half_rn(W1[((size_t)tap * CDIM + k) * FDIM + f]);
    }
}

// ---------------- neighbor maps --------------------------------------------
__global__ void prevnext_kernel(const int* __restrict__ index) {
    int t = blockIdx.x * blockDim.x + threadIdx.x;
    if (t >= NCOLS * N_PTS) return;
    int i = t / NCOLS;
    int c = t % NCOLS;
    int p = index[t];
    g_prev[c * N_PTS + p] = (i > 0)         ? index[t - NCOLS] : -1;
    g_next[c * N_PTS + p] = (i < N_PTS - 1) ? index[t + NCOLS] : -1;
}

// ============ fp16 HMMA GEMM:  C[M,288] = Ah[M,K] @ Bh[288,K]^T ============
// 1-pass both stages; 3-stage cp.async pipeline.
// CTA: BM=128, BN=96, BK=32. 12 warps 4(M) x 3(N); warp tile 32x32.
// Grid (3, 1563): N-tiles fastest -> A re-reads hit L2.
// smem per buf: Ah 128x80B + Bh 96x80B = 17920 B; 3 bufs = 53760 -> 2 CTAs/SM.
#define N_MTILE  1563                // ceil(200000/128)
#define NTHR     384
#define ABYTES   10240               // 128 rows x 80B
#define BUF_SZ   17920
#define NSTAGE   3
#define GSM_TOTAL (NSTAGE * BUF_SZ)  // 53760

template <int KDIM>
__device__ __forceinline__ void gemm_stage(
        int tid, int row0, int col0, int k0, int buf,
        const __half* __restrict__ Ahp,
        const __half* __restrict__ Bhp,
        uint32_t sb) {
    uint32_t base = sb + buf * BUF_SZ;
    // A: 128 rows x 32 k fp16 = 512 x 16B
    for (int idx = tid; idx < 512; idx += NTHR) {
        int r = idx >> 2, c = idx & 3;
        int gr = row0 + r;
        uint32_t sz = (gr < N_PTS) ? 16u : 0u;
        cp16p(base + (uint32_t)(r * 80 + c * 16),
              Ahp + (size_t)gr * KDIM + k0 + c * 8, sz);
    }
    // B: 96 rows x 32 k = 384 x 16B; exactly one per thread
    {
        int r = tid >> 2, c = tid & 3;
        size_t go = (size_t)(col0 + r) * KDIM + k0 + c * 8;
        cp16(base + ABYTES + (uint32_t)(r * 80 + c * 16), Bhp + go);
    }
}

template <int STAGE>
__global__ __launch_bounds__(NTHR, 2)
void mma_gemm_kernel() {
    constexpr int KDIM = (STAGE == 1) ? CDIM : HDIM;
    constexpr int NCH  = KDIM / 32;
    const __half* __restrict__ Ahp = (STAGE == 1) ? g_Xh : g_hh;
    const __half* __restrict__ Bhp = (STAGE == 1) ? g_B1h : g_B2h;
    float* __restrict__ C = (STAGE == 1) ? g_Z : g_Zh;

    extern __shared__ char smem[];
    const uint32_t sb = smem_u32(smem);

    const int tid  = threadIdx.x;
    const int wid  = tid >> 5;
    const int lane = tid & 31;
    const int g    = lane >> 2;        // 0..7
    const int tg   = lane & 3;         // 0..3
    const int wm   = wid & 3;          // M warp 0..3
    const int wn   = wid >> 2;         // N warp 0..2
    const int row0 = blockIdx.y * 128; // M tile (slow grid dim)
    const int col0 = blockIdx.x * 96;  // N tile (fast grid dim -> L2 reuse)

    // ldmatrix lane addressing (byte offsets within a buffer)
    const uint32_t a_lrow = (uint32_t)(wm * 32 + (lane & 15));
    const uint32_t a_loff = a_lrow * 80 + ((lane >> 4) * 16);
    const uint32_t b_lrow = (uint32_t)(wn * 32 + (lane & 7) + (((lane >> 4) & 1) * 8));
    const uint32_t b_loff = b_lrow * 80 + (((lane >> 3) & 1) * 16);

    float acc[2][4][4];
    #pragma unroll
    for (int mf = 0; mf < 2; mf++)
        #pragma unroll
        for (int nf = 0; nf < 4; nf++)
            #pragma unroll
            for (int i = 0; i < 4; i++) acc[mf][nf][i] = 0.f;

    #pragma unroll
    for (int s = 0; s < NSTAGE - 1; s++) {
        gemm_stage<KDIM>(tid, row0, col0, s * 32, s, Ahp, Bhp, sb);
        CP_COMMIT();
    }

    for (int kc = 0; kc < NCH; kc++) {
        if (kc + NSTAGE - 1 < NCH) {
            gemm_stage<KDIM>(tid, row0, col0, (kc + NSTAGE - 1) * 32,
                             (kc + NSTAGE - 1) % NSTAGE, Ahp, Bhp, sb);
            CP_COMMIT();
            asm volatile("cp.async.wait_group %0;" :: "n"(NSTAGE - 1) : "memory");
        } else if (kc + 1 < NCH) {
            asm volatile("cp.async.wait_group 1;" ::: "memory");
        } else {
            asm volatile("cp.async.wait_group 0;" ::: "memory");
        }
        __syncthreads();

        const uint32_t base = sb + (kc % NSTAGE) * BUF_SZ;

        #pragma unroll
        for (int ks = 0; ks < 2; ks++) {
            const uint32_t kb = ks * 32;           // 16 f16 = 32 bytes
            uint32_t AH[2][4];
            #pragma unroll
            for (int mf = 0; mf < 2; mf++)
                ldm_x4(AH[mf], base + a_loff + mf * (16 * 80) + kb);
            #pragma unroll
            for (int pnf = 0; pnf < 2; pnf++) {
                uint32_t bd = base + ABYTES + b_loff + pnf * (16 * 80) + kb;
                uint32_t BH4[4];
                ldm_x4(BH4, bd);
                #pragma unroll
                for (int half = 0; half < 2; half++) {
                    const uint32_t* bh = BH4 + half * 2;
                    mma_f16(acc[0][pnf * 2 + half], AH[0], bh);
                    mma_f16(acc[1][pnf * 2 + half], AH[1], bh);
                }
            }
        }
        __syncthreads();
    }

    // epilogue: fp32 accumulators -> C
    #pragma unroll
    for (int mf = 0; mf < 2; mf++) {
        int row = row0 + wm * 32 + mf * 16 + g;
        #pragma unroll
        for (int nf = 0; nf < 4; nf++) {
            int col = col0 + wn * 32 + nf * 8 + 2 * tg;
            if (row < N_PTS)
                *(float2*)(C + (size_t)row * HDIM + col) =
                    make_float2(acc[mf][nf][0], acc[mf][nf][1]);
            if (row + 8 < N_PTS)
                *(float2*)(C + (size_t)(row + 8) * HDIM + col) =
                    make_float2(acc[mf][nf][2], acc[mf][nf][3]);
        }
    }
}

// -------- assemble stage 1:  h = relu(b1 + 3 gathered taps) -> fp16 --------
__global__ __launch_bounds__(256)
void assemble1_kernel(const float* __restrict__ b1) {
    int idx = blockIdx.x * 256 + threadIdx.x;      // N_PTS * 72 float4 tasks
    if (idx >= N_PTS * 72) return;
    int p = idx / 72;
    int gidx = idx - p * 72;
    int c = gidx / 24;          // tap 0..2
    int j = gidx - c * 24;      // float4 within 96
    int prev = g_prev[c * N_PTS + p];
    int next = g_next[c * N_PTS + p];
    float4 v = ((const float4*)b1)[j];
    if (prev >= 0) {
        float4 z = *(const float4*)(g_Z + (size_t)prev * HDIM + j * 4);
        v.x += z.x; v.y += z.y; v.z += z.z; v.w += z.w;
    }
    {
        float4 z = *(const float4*)(g_Z + (size_t)p * HDIM + FDIM + j * 4);
        v.x += z.x; v.y += z.y; v.z += z.z; v.w += z.w;
    }
    if (next >= 0) {
        float4 z = *(const float4*)(g_Z + (size_t)next * HDIM + 2 * FDIM + j * 4);
        v.x += z.x; v.y += z.y; v.z += z.z; v.w += z.w;
    }
    __half2 h0 = __floats2half2_rn(fmaxf(v.x, 0.f), fmaxf(v.y, 0.f));
    __half2 h1 = __floats2half2_rn(fmaxf(v.z, 0.f), fmaxf(v.w, 0.f));
    int o = p * 72 + c * 24 + j;                   // uint2 (4-elem) index
    ((uint2*)g_hh)[o] = make_uint2(*(uint32_t*)&h0, *(uint32_t*)&h1);
}

// ------- assemble stage 2 + residual + layernorm (warp per point) ----------
__global__ __launch_bounds__(256)
void assemble2_ln_kernel(const float* __restrict__ b2,
                         const float* __restrict__ gamma,
                         const float* __restrict__ beta,
                         float* __restrict__ out) {
    int p    = (blockIdx.x * 256 + threadIdx.x) >> 5;   // warp per point
    int lane = threadIdx.x & 31;
    float4 xv[3];
    float s = 0.f, q = 0.f;
    if (lane < 24) {
        #pragma unroll
        for (int c = 0; c < 3; c++) {
            int prev = g_prev[c * N_PTS + p];
            int next = g_next[c * N_PTS + p];
            float4 v = ((const float4*)b2)[lane];
            if (prev >= 0) {
                float4 z = *(const float4*)(g_Zh + (size_t)prev * HDIM + lane * 4);
                v.x += z.x; v.y += z.y; v.z += z.z; v.w += z.w;
            }
            {
                float4 z = *(const float4*)(g_Zh + (size_t)p * HDIM + FDIM + lane * 4);
                v.x += z.x; v.y += z.y; v.z += z.z; v.w += z.w;
            }
            if (next >= 0) {
                float4 z = *(const float4*)(g_Zh + (size_t)next * HDIM + 2 * FDIM + lane * 4);
                v.x += z.x; v.y += z.y; v.z += z.z; v.w += z.w;
            }
            int o = p * 72 + c * 24 + lane;
            uint2 hh = ((const uint2*)g_hh)[o];
            float2 a0 = up2(hh.x), a1 = up2(hh.y);
            float4 x;
            x.x = a0.x + fmaxf(v.x, 0.f);
            x.y = a0.y + fmaxf(v.y, 0.f);
            x.z = a1.x + fmaxf(v.z, 0.f);
            x.w = a1.y + fmaxf(v.w, 0.f);
            xv[c] = x;
            s += x.x + x.y + x.z + x.w;
            q += x.x * x.x + x.y * x.y + x.z * x.z + x.w * x.w;
        }
    }
    #pragma unroll
    for (int o = 16; o > 0; o >>= 1) {
        s += __shfl_xor_sync(0xffffffffu, s, o);
        q += __shfl_xor_sync(0xffffffffu, q, o);
    }
    float mu  = s * (1.f / HDIM);
    float var = q * (1.f / HDIM) - mu * mu;
    float r   = rsqrtf(var + EPSV);
    if (lane < 24) {
        #pragma unroll
        for (int c = 0; c < 3; c++) {
            float4 gm = ((const float4*)gamma)[c * 24 + lane];
            float4 bt = ((const float4*)beta)[c * 24 + lane];
            float4 x  = xv[c];
            float4 o4;
            o4.x = (x.x - mu) * r * gm.x + bt.x;
            o4.y = (x.y - mu) * r * gm.y + bt.y;
            o4.z = (x.z - mu) * r * gm.z + bt.z;
            o4.w = (x.w - mu) * r * gm.w + bt.w;
            *(float4*)(out + (size_t)p * HDIM + c * FDIM + lane * 4) = o4;
        }
    }
}

// ---------------- index pass-through tail ----------------------------------
__global__ void copy_index_kernel(const int* __restrict__ index,
                                  float* __restrict__ out, int count) {
    int t = blockIdx.x * blockDim.x + threadIdx.x;
    if (t < count) out[t] = (float)index[t];
}

// ---------------------------------------------------------------------------
extern "C" void kernel_launch(void* const* d_in, const int* in_sizes, int n_in,
                              void* d_out, int out_size) {
    const float* X     = (const float*)d_in[0];
    const int*   index = (const int*)  d_in[1];
    const float* W1    = (const float*)d_in[2];
    const float* b1    = (const float*)d_in[3];
    const float* W2    = (const float*)d_in[4];
    const float* b2    = (const float*)d_in[5];
    const float* gamma = (const float*)d_in[6];
    const float* beta  = (const float*)d_in[7];
    float* out = (float*)d_out;

    cudaFuncSetAttribute(mma_gemm_kernel<1>,
                         cudaFuncAttributeMaxDynamicSharedMemorySize, GSM_TOTAL);
    cudaFuncSetAttribute(mma_gemm_kernel<2>,
                         cudaFuncAttributeMaxDynamicSharedMemorySize, GSM_TOTAL);

    split_x_kernel<<<(N_PTS * 24 + 255) / 256, 256>>>(X);
    pack_w_kernel<<<(HDIM * HDIM + 255) / 256, 256>>>(W1, W2);
    prevnext_kernel<<<(NCOLS * N_PTS + 255) / 256, 256>>>(index);

    dim3 gg(3, N_MTILE);                          // N fastest -> A L2 reuse
    mma_gemm_kernel<1><<<gg, NTHR, GSM_TOTAL>>>();        // Z  = Xh @ B1h^T
    assemble1_kernel<<<(N_PTS * 72 + 255) / 256, 256>>>(b1);
    mma_gemm_kernel<2><<<gg, NTHR, GSM_TOTAL>>>();        // Zh = hh @ B2h^T
    assemble2_ln_kernel<<<(N_PTS * 32 + 255) / 256, 256>>>(b2, gamma, beta, out);

    int tail = out_size - N_PTS * HDIM;
    if (tail > 0) {
        if (tail > NCOLS * N_PTS) tail = NCOLS * N_PTS;
        copy_index_kernel<<<(tail + 255) / 256, 256>>>(
            index, out + (size_t)N_PTS * HDIM, tail);
    }
}

// round 13
// speedup vs baseline: 2.2341x; 1.1447x over previous
#include <cuda_runtime.h>
#include <cuda_fp16.h>
#include <cstdint>

#define N_PTS 200000
#define CDIM 96
#define FDIM 96
#define NCOLS 3
#define HDIM 288          // NCOLS * FDIM
#define EPSV 1e-3f

// ---------------- scratch (device globals: no allocation allowed) ----------
__device__ __half g_Z [(size_t)N_PTS * HDIM];  // stage-1 GEMM out (fp16)
__device__ __half g_Zh[(size_t)N_PTS * HDIM];  // stage-2 GEMM out (fp16)
__device__ int   g_prev[NCOLS * N_PTS];
__device__ int   g_next[NCOLS * N_PTS];
// A operands in fp16 (hi only — dropped low terms are ~2^-11 relative)
__device__ __half g_Xh[(size_t)N_PTS * CDIM];
__device__ __half g_hh[(size_t)N_PTS * HDIM];
// fp16 weights, MMA layout: B[n][k]  (n = tap*FDIM + f)
__device__ __half g_B1h[HDIM * CDIM];
__device__ __half g_B2h[HDIM * HDIM];

// ======================= helpers ==========================================
__device__ __forceinline__ uint32_t smem_u32(const void* p) {
    uint32_t a;
    asm("{ .reg .u64 t; cvta.to.shared.u64 t, %1; cvt.u32.u64 %0, t; }"
        : "=r"(a) : "l"(p));
    return a;
}
// .cg: bypass L1 (keep L1 free for ldmatrix traffic)
__device__ __forceinline__ void cp16(uint32_t dst, const void* src) {
    asm volatile("cp.async.cg.shared.global [%0], [%1], 16;"
                 :: "r"(dst), "l"(src) : "memory");
}
__device__ __forceinline__ void cp16p(uint32_t dst, const void* src, uint32_t sz) {
    asm volatile("cp.async.cg.shared.global [%0], [%1], 16, %2;"
                 :: "r"(dst), "l"(src), "r"(sz) : "memory");
}
#define CP_COMMIT() asm volatile("cp.async.commit_group;" ::: "memory")

__device__ __forceinline__ void ldm_x4(uint32_t* r, uint32_t addr) {
    asm volatile("ldmatrix.sync.aligned.m8n8.x4.shared.b16 {%0,%1,%2,%3}, [%4];"
                 : "=r"(r[0]), "=r"(r[1]), "=r"(r[2]), "=r"(r[3]) : "r"(addr));
}

// D += A*B  (m16n8k16, fp16 in, fp32 acc)
__device__ __forceinline__ void mma_f16(float* d, const uint32_t* a,
                                        const uint32_t* b) {
    asm volatile(
        "mma.sync.aligned.m16n8k16.row.col.f32.f16.f16.f32 "
        "{%0,%1,%2,%3}, {%4,%5,%6,%7}, {%8,%9}, {%0,%1,%2,%3};"
        : "+f"(d[0]), "+f"(d[1]), "+f"(d[2]), "+f"(d[3])
        : "r"(a[0]), "r"(a[1]), "r"(a[2]), "r"(a[3]), "r"(b[0]), "r"(b[1]));
}

// f16x2 word -> float2 (exact)
__device__ __forceinline__ float2 up2(uint32_t u) {
    __half2 h = *reinterpret_cast<__half2*>(&u);
    return __half22float2(h);
}

// ---------------- convert X to fp16 -----------------------------------------
__global__ void split_x_kernel(const float* __restrict__ X) {
    int idx = blockIdx.x * 256 + threadIdx.x;        // groups of 4 floats
    if (idx >= N_PTS * (CDIM / 4)) return;
    float4 v = ((const float4*)X)[idx];
    __half2 h0 = __floats2half2_rn(v.x, v.y);
    __half2 h1 = __floats2half2_rn(v.z, v.w);
    ((uint2*)g_Xh)[idx] = make_uint2(*(uint32_t*)&h0, *(uint32_t*)&h1);
}

// ---------------- pack weights: fp16, [n][k] MMA layout --------------------
__global__ void pack_w_kernel(const float* __restrict__ W1,
                              const float* __restrict__ W2) {
    int t = blockIdx.x * blockDim.x + threadIdx.x;
    if (t < HDIM * HDIM) {                       // W2: (3, 288, 96)
        int n = t / HDIM, k = t % HDIM;
        int tap = n / FDIM, f = n % FDIM;
        g_B2h[(size_t)n * HDIM + k] =
            __float2half_rn(W2[((size_t)tap * HDIM + k) * FDIM + f]);
    }
    if (t < HDIM * CDIM) {                       // W1: (3, 96, 96)
        int n = t / CDIM, k = t % CDIM;
        int tap = n / FDIM, f = n % FDIM;
        g_B1h[(size_t)n * CDIM + k] =
            __float2half_rn(W1[((size_t)tap * CDIM + k) * FDIM + f]);
    }
}

// ---------------- neighbor maps --------------------------------------------
__global__ void prevnext_kernel(const int* __restrict__ index) {
    int t = blockIdx.x * blockDim.x + threadIdx.x;
    if (t >= NCOLS * N_PTS) return;
    int i = t / NCOLS;
    int c = t % NCOLS;
    int p = index[t];
    g_prev[c * N_PTS + p] = (i > 0)         ? index[t - NCOLS] : -1;
    g_next[c * N_PTS + p] = (i < N_PTS - 1) ? index[t + NCOLS] : -1;
}

// ============ fp16 HMMA GEMM:  C[M,288] = Ah[M,K] @ Bh[288,K]^T ============
// 1-pass both stages; 3-stage cp.async pipeline; fp16 output.
// CTA: BM=128, BN=96, BK=32. 12 warps 4(M) x 3(N); warp tile 32x32.
// Grid (3, 1563): N-tiles fastest -> A re-reads hit L2.
#define N_MTILE  1563                // ceil(200000/128)
#define NTHR     384
#define ABYTES   10240               // 128 rows x 80B
#define BUF_SZ   17920
#define NSTAGE   3
#define GSM_TOTAL (NSTAGE * BUF_SZ)  // 53760

template <int KDIM>
__device__ __forceinline__ void gemm_stage(
        int tid, int row0, int col0, int k0, int buf,
        const __half* __restrict__ Ahp,
        const __half* __restrict__ Bhp,
        uint32_t sb) {
    uint32_t base = sb + buf * BUF_SZ;
    // A: 128 rows x 32 k fp16 = 512 x 16B
    for (int idx = tid; idx < 512; idx += NTHR) {
        int r = idx >> 2, c = idx & 3;
        int gr = row0 + r;
        uint32_t sz = (gr < N_PTS) ? 16u : 0u;
        cp16p(base + (uint32_t)(r * 80 + c * 16),
              Ahp + (size_t)gr * KDIM + k0 + c * 8, sz);
    }
    // B: 96 rows x 32 k = 384 x 16B; exactly one per thread
    {
        int r = tid >> 2, c = tid & 3;
        size_t go = (size_t)(col0 + r) * KDIM + k0 + c * 8;
        cp16(base + ABYTES + (uint32_t)(r * 80 + c * 16), Bhp + go);
    }
}

template <int STAGE>
__global__ __launch_bounds__(NTHR, 2)
void mma_gemm_kernel() {
    constexpr int KDIM = (STAGE == 1) ? CDIM : HDIM;
    constexpr int NCH  = KDIM / 32;
    const __half* __restrict__ Ahp = (STAGE == 1) ? g_Xh : g_hh;
    const __half* __restrict__ Bhp = (STAGE == 1) ? g_B1h : g_B2h;
    __half* __restrict__ C = (STAGE == 1) ? g_Z : g_Zh;

    extern __shared__ char smem[];
    const uint32_t sb = smem_u32(smem);

    const int tid  = threadIdx.x;
    const int wid  = tid >> 5;
    const int lane = tid & 31;
    const int g    = lane >> 2;        // 0..7
    const int tg   = lane & 3;         // 0..3
    const int wm   = wid & 3;          // M warp 0..3
    const int wn   = wid >> 2;         // N warp 0..2
    const int row0 = blockIdx.y * 128; // M tile (slow grid dim)
    const int col0 = blockIdx.x * 96;  // N tile (fast grid dim -> L2 reuse)

    // ldmatrix lane addressing (byte offsets within a buffer)
    const uint32_t a_lrow = (uint32_t)(wm * 32 + (lane & 15));
    const uint32_t a_loff = a_lrow * 80 + ((lane >> 4) * 16);
    const uint32_t b_lrow = (uint32_t)(wn * 32 + (lane & 7) + (((lane >> 4) & 1) * 8));
    const uint32_t b_loff = b_lrow * 80 + (((lane >> 3) & 1) * 16);

    float acc[2][4][4];
    #pragma unroll
    for (int mf = 0; mf < 2; mf++)
        #pragma unroll
        for (int nf = 0; nf < 4; nf++)
            #pragma unroll
            for (int i = 0; i < 4; i++) acc[mf][nf][i] = 0.f;

    #pragma unroll
    for (int s = 0; s < NSTAGE - 1; s++) {
        gemm_stage<KDIM>(tid, row0, col0, s * 32, s, Ahp, Bhp, sb);
        CP_COMMIT();
    }

    for (int kc = 0; kc < NCH; kc++) {
        if (kc + NSTAGE - 1 < NCH) {
            gemm_stage<KDIM>(tid, row0, col0, (kc + NSTAGE - 1) * 32,
                             (kc + NSTAGE - 1) % NSTAGE, Ahp, Bhp, sb);
            CP_COMMIT();
            asm volatile("cp.async.wait_group %0;" :: "n"(NSTAGE - 1) : "memory");
        } else if (kc + 1 < NCH) {
            asm volatile("cp.async.wait_group 1;" ::: "memory");
        } else {
            asm volatile("cp.async.wait_group 0;" ::: "memory");
        }
        __syncthreads();

        const uint32_t base = sb + (kc % NSTAGE) * BUF_SZ;

        #pragma unroll
        for (int ks = 0; ks < 2; ks++) {
            const uint32_t kb = ks * 32;           // 16 f16 = 32 bytes
            uint32_t AH[2][4];
            #pragma unroll
            for (int mf = 0; mf < 2; mf++)
                ldm_x4(AH[mf], base + a_loff + mf * (16 * 80) + kb);
            #pragma unroll
            for (int pnf = 0; pnf < 2; pnf++) {
                uint32_t bd = base + ABYTES + b_loff + pnf * (16 * 80) + kb;
                uint32_t BH4[4];
                ldm_x4(BH4, bd);
                #pragma unroll
                for (int half = 0; half < 2; half++) {
                    const uint32_t* bh = BH4 + half * 2;
                    mma_f16(acc[0][pnf * 2 + half], AH[0], bh);
                    mma_f16(acc[1][pnf * 2 + half], AH[1], bh);
                }
            }
        }
        __syncthreads();
    }

    // epilogue: fp32 accumulators -> fp16 C
    #pragma unroll
    for (int mf = 0; mf < 2; mf++) {
        int row = row0 + wm * 32 + mf * 16 + g;
        #pragma unroll
        for (int nf = 0; nf < 4; nf++) {
            int col = col0 + wn * 32 + nf * 8 + 2 * tg;
            if (row < N_PTS) {
                __half2 v = __floats2half2_rn(acc[mf][nf][0], acc[mf][nf][1]);
                *(uint32_t*)(C + (size_t)row * HDIM + col) = *(uint32_t*)&v;
            }
            if (row + 8 < N_PTS) {
                __half2 v = __floats2half2_rn(acc[mf][nf][2], acc[mf][nf][3]);
                *(uint32_t*)(C + (size_t)(row + 8) * HDIM + col) = *(uint32_t*)&v;
            }
        }
    }
}

// -------- assemble stage 1:  h = relu(b1 + 3 gathered taps) -> fp16 --------
__global__ __launch_bounds__(256)
void assemble1_kernel(const float* __restrict__ b1) {
    int idx = blockIdx.x * 256 + threadIdx.x;      // N_PTS * 72 tasks (4 elems)
    if (idx >= N_PTS * 72) return;
    int p = idx / 72;
    int gidx = idx - p * 72;
    int c = gidx / 24;          // tap 0..2
    int j = gidx - c * 24;      // 4-elem group within 96
    int prev = g_prev[c * N_PTS + p];
    int next = g_next[c * N_PTS + p];
    float4 v = ((const float4*)b1)[j];
    if (prev >= 0) {
        uint2 z = *(const uint2*)(g_Z + (size_t)prev * HDIM + j * 4);
        float2 z0 = up2(z.x), z1 = up2(z.y);
        v.x += z0.x; v.y += z0.y; v.z += z1.x; v.w += z1.y;
    }
    {
        uint2 z = *(const uint2*)(g_Z + (size_t)p * HDIM + FDIM + j * 4);
        float2 z0 = up2(z.x), z1 = up2(z.y);
        v.x += z0.x; v.y += z0.y; v.z += z1.x; v.w += z1.y;
    }
    if (next >= 0) {
        uint2 z = *(const uint2*)(g_Z + (size_t)next * HDIM + 2 * FDIM + j * 4);
        float2 z0 = up2(z.x), z1 = up2(z.y);
        v.x += z0.x; v.y += z0.y; v.z += z1.x; v.w += z1.y;
    }
    __half2 h0 = __floats2half2_rn(fmaxf(v.x, 0.f), fmaxf(v.y, 0.f));
    __half2 h1 = __floats2half2_rn(fmaxf(v.z, 0.f), fmaxf(v.w, 0.f));
    int o = p * 72 + c * 24 + j;                   // uint2 (4-elem) index
    ((uint2*)g_hh)[o] = make_uint2(*(uint32_t*)&h0, *(uint32_t*)&h1);
}

// ------- assemble stage 2 + residual + layernorm (warp per point) ----------
__global__ __launch_bounds__(256)
void assemble2_ln_kernel(const float* __restrict__ b2,
                         const float* __restrict__ gamma,
                         const float* __restrict__ beta,
                         float* __restrict__ out) {
    int p    = (blockIdx.x * 256 + threadIdx.x) >> 5;   // warp per point
    int lane = threadIdx.x & 31;
    float4 xv[3];
    float s = 0.f, q = 0.f;
    if (lane < 24) {
        #pragma unroll
        for (int c = 0; c < 3; c++) {
            int prev = g_prev[c * N_PTS + p];
            int next = g_next[c * N_PTS + p];
            float4 v = ((const float4*)b2)[lane];
            if (prev >= 0) {
                uint2 z = *(const uint2*)(g_Zh + (size_t)prev * HDIM + lane * 4);
                float2 z0 = up2(z.x), z1 = up2(z.y);
                v.x += z0.x; v.y += z0.y; v.z += z1.x; v.w += z1.y;
            }
            {
                uint2 z = *(const uint2*)(g_Zh + (size_t)p * HDIM + FDIM + lane * 4);
                float2 z0 = up2(z.x), z1 = up2(z.y);
                v.x += z0.x; v.y += z0.y; v.z += z1.x; v.w += z1.y;
            }
            if (next >= 0) {
                uint2 z = *(const uint2*)(g_Zh + (size_t)next * HDIM + 2 * FDIM + lane * 4);
                float2 z0 = up2(z.x), z1 = up2(z.y);
                v.x += z0.x; v.y += z0.y; v.z += z1.x; v.w += z1.y;
            }
            int o = p * 72 + c * 24 + lane;
            uint2 hh = ((const uint2*)g_hh)[o];
            float2 a0 = up2(hh.x), a1 = up2(hh.y);
            float4 x;
            x.x = a0.x + fmaxf(v.x, 0.f);
            x.y = a0.y + fmaxf(v.y, 0.f);
            x.z = a1.x + fmaxf(v.z, 0.f);
            x.w = a1.y + fmaxf(v.w, 0.f);
            xv[c] = x;
            s += x.x + x.y + x.z + x.w;
            q += x.x * x.x + x.y * x.y + x.z * x.z + x.w * x.w;
        }
    }
    #pragma unroll
    for (int o = 16; o > 0; o >>= 1) {
        s += __shfl_xor_sync(0xffffffffu, s, o);
        q += __shfl_xor_sync(0xffffffffu, q, o);
    }
    float mu  = s * (1.f / HDIM);
    float var = q * (1.f / HDIM) - mu * mu;
    float r   = rsqrtf(var + EPSV);
    if (lane < 24) {
        #pragma unroll
        for (int c = 0; c < 3; c++) {
            float4 gm = ((const float4*)gamma)[c * 24 + lane];
            float4 bt = ((const float4*)beta)[c * 24 + lane];
            float4 x  = xv[c];
            float4 o4;
            o4.x = (x.x - mu) * r * gm.x + bt.x;
            o4.y = (x.y - mu) * r * gm.y + bt.y;
            o4.z = (x.z - mu) * r * gm.z + bt.z;
            o4.w = (x.w - mu) * r * gm.w + bt.w;
            *(float4*)(out + (size_t)p * HDIM + c * FDIM + lane * 4) = o4;
        }
    }
}

// ---------------- index pass-through tail ----------------------------------
__global__ void copy_index_kernel(const int* __restrict__ index,
                                  float* __restrict__ out, int count) {
    int t = blockIdx.x * blockDim.x + threadIdx.x;
    if (t < count) out[t] = (float)index[t];
}

// ---------------------------------------------------------------------------
extern "C" void kernel_launch(void* const* d_in, const int* in_sizes, int n_in,
                              void* d_out, int out_size) {
    const float* X     = (const float*)d_in[0];
    const int*   index = (const int*)  d_in[1];
    const float* W1    = (const float*)d_in[2];
    const float* b1    = (const float*)d_in[3];
    const float* W2    = (const float*)d_in[4];
    const float* b2    = (const float*)d_in[5];
    const float* gamma = (const float*)d_in[6];
    const float* beta  = (const float*)d_in[7];
    float* out = (float*)d_out;

    cudaFuncSetAttribute(mma_gemm_kernel<1>,
                         cudaFuncAttributeMaxDynamicSharedMemorySize, GSM_TOTAL);
    cudaFuncSetAttribute(mma_gemm_kernel<2>,
                         cudaFuncAttributeMaxDynamicSharedMemorySize, GSM_TOTAL);

    split_x_kernel<<<(N_PTS * 24 + 255) / 256, 256>>>(X);
    pack_w_kernel<<<(HDIM * HDIM + 255) / 256, 256>>>(W1, W2);
    prevnext_kernel<<<(NCOLS * N_PTS + 255) / 256, 256>>>(index);

    dim3 gg(3, N_MTILE);                          // N fastest -> A L2 reuse
    mma_gemm_kernel<1><<<gg, NTHR, GSM_TOTAL>>>();        // Z  = Xh @ B1h^T
    assemble1_kernel<<<(N_PTS * 72 + 255) / 256, 256>>>(b1);
    mma_gemm_kernel<2><<<gg, NTHR, GSM_TOTAL>>>();        // Zh = hh @ B2h^T
    assemble2_ln_kernel<<<(N_PTS * 32 + 255) / 256, 256>>>(b2, gamma, beta, out);

    int tail = out_size - N_PTS * HDIM;
    if (tail > 0) {
        if (tail > NCOLS * N_PTS) tail = NCOLS * N_PTS;
        copy_index_kernel<<<(tail + 255) / 256, 256>>>(
            index, out + (size_t)N_PTS * HDIM, tail);
    }
}

// round 14
// speedup vs baseline: 2.3330x; 1.0443x over previous
#include <cuda_runtime.h>
#include <cuda_fp16.h>
#include <cstdint>

#define N_PTS 200000
#define CDIM 96
#define FDIM 96
#define NCOLS 3
#define HDIM 288          // NCOLS * FDIM
#define EPSV 1e-3f

// ---------------- scratch (device globals: no allocation allowed) ----------
__device__ __half g_Z [(size_t)N_PTS * HDIM];  // stage-1 GEMM out (fp16)
__device__ __half g_Zh[(size_t)N_PTS * HDIM];  // stage-2 GEMM out (fp16)
__device__ int   g_prev[NCOLS * N_PTS];
__device__ int   g_next[NCOLS * N_PTS];
// A operands in fp16 (hi only — dropped low terms are ~2^-11 relative)
__device__ __half g_Xh[(size_t)N_PTS * CDIM];
__device__ __half g_hh[(size_t)N_PTS * HDIM];
// fp16 weights, MMA layout: B[n][k]  (n = tap*FDIM + f)
__device__ __half g_B1h[HDIM * CDIM];
__device__ __half g_B2h[HDIM * HDIM];

// ======================= helpers ==========================================
__device__ __forceinline__ uint32_t smem_u32(const void* p) {
    uint32_t a;
    asm("{ .reg .u64 t; cvta.to.shared.u64 t, %1; cvt.u32.u64 %0, t; }"
        : "=r"(a) : "l"(p));
    return a;
}
// .cg: bypass L1 (keep L1 free for ldmatrix traffic)
__device__ __forceinline__ void cp16(uint32_t dst, const void* src) {
    asm volatile("cp.async.cg.shared.global [%0], [%1], 16;"
                 :: "r"(dst), "l"(src) : "memory");
}
__device__ __forceinline__ void cp16p(uint32_t dst, const void* src, uint32_t sz) {
    asm volatile("cp.async.cg.shared.global [%0], [%1], 16, %2;"
                 :: "r"(dst), "l"(src), "r"(sz) : "memory");
}
#define CP_COMMIT() asm volatile("cp.async.commit_group;" ::: "memory")

__device__ __forceinline__ void ldm_x4(uint32_t* r, uint32_t addr) {
    asm volatile("ldmatrix.sync.aligned.m8n8.x4.shared.b16 {%0,%1,%2,%3}, [%4];"
                 : "=r"(r[0]), "=r"(r[1]), "=r"(r[2]), "=r"(r[3]) : "r"(addr));
}

// D += A*B  (m16n8k16, fp16 in, fp32 acc)
__device__ __forceinline__ void mma_f16(float* d, const uint32_t* a,
                                        const uint32_t* b) {
    asm volatile(
        "mma.sync.aligned.m16n8k16.row.col.f32.f16.f16.f32 "
        "{%0,%1,%2,%3}, {%4,%5,%6,%7}, {%8,%9}, {%0,%1,%2,%3};"
        : "+f"(d[0]), "+f"(d[1]), "+f"(d[2]), "+f"(d[3])
        : "r"(a[0]), "r"(a[1]), "r"(a[2]), "r"(a[3]), "r"(b[0]), "r"(b[1]));
}

// f16x2 word -> float2 (exact)
__device__ __forceinline__ float2 up2(uint32_t u) {
    __half2 h = *reinterpret_cast<__half2*>(&u);
    return __half22float2(h);
}

// ---------------- convert X to fp16 -----------------------------------------
__global__ void split_x_kernel(const float* __restrict__ X) {
    int idx = blockIdx.x * 256 + threadIdx.x;        // groups of 4 floats
    if (idx >= N_PTS * (CDIM / 4)) return;
    float4 v = ((const float4*)X)[idx];
    __half2 h0 = __floats2half2_rn(v.x, v.y);
    __half2 h1 = __floats2half2_rn(v.z, v.w);
    ((uint2*)g_Xh)[idx] = make_uint2(*(uint32_t*)&h0, *(uint32_t*)&h1);
}

// ---------------- pack weights: fp16, [n][k] MMA layout --------------------
__global__ void pack_w_kernel(const float* __restrict__ W1,
                              const float* __restrict__ W2) {
    int t = blockIdx.x * blockDim.x + threadIdx.x;
    if (t < HDIM * HDIM) {                       // W2: (3, 288, 96)
        int n = t / HDIM, k = t % HDIM;
        int tap = n / FDIM, f = n % FDIM;
        g_B2h[(size_t)n * HDIM + k] =
            __float2half_rn(W2[((size_t)tap * HDIM + k) * FDIM + f]);
    }
    if (t < HDIM * CDIM) {                       // W1: (3, 96, 96)
        int n = t / CDIM, k = t % CDIM;
        int tap = n / FDIM, f = n % FDIM;
        g_B1h[(size_t)n * CDIM + k] =
            __float2half_rn(W1[((size_t)tap * CDIM + k) * FDIM + f]);
    }
}

// ---------------- neighbor maps --------------------------------------------
__global__ void prevnext_kernel(const int* __restrict__ index) {
    int t = blockIdx.x * blockDim.x + threadIdx.x;
    if (t >= NCOLS * N_PTS) return;
    int i = t / NCOLS;
    int c = t % NCOLS;
    int p = index[t];
    g_prev[c * N_PTS + p] = (i > 0)         ? index[t - NCOLS] : -1;
    g_next[c * N_PTS + p] = (i < N_PTS - 1) ? index[t + NCOLS] : -1;
}

// ============ fp16 HMMA GEMM:  C[M,288] = Ah[M,K] @ Bh[288,K]^T ============
// BK=96: GEMM1 = single chunk (no pipeline), GEMM2 = 3 chunks, 2-stage ring.
// CTA: BM=128, BN=96. 12 warps 4(M) x 3(N); warp tile 32x32.
// Grid (3, 1563): N-tiles fastest -> A re-reads hit L2.
// Row stride 208B (192B data + 16B pad; 208 % 128 == 80 -> conflict-free).
#define N_MTILE  1563                // ceil(200000/128)
#define NTHR     384
#define RSTRIDE  208
#define ABYTES   (128 * RSTRIDE)     // 26624
#define BUF_SZ   ((128 + 96) * RSTRIDE)   // 46592
#define NSTAGE   2
#define GSM_TOTAL (NSTAGE * BUF_SZ)  // 93184

template <int KDIM>
__device__ __forceinline__ void gemm_stage(
        int tid, int row0, int col0, int k0, int buf,
        const __half* __restrict__ Ahp,
        const __half* __restrict__ Bhp,
        uint32_t sb) {
    uint32_t base = sb + buf * BUF_SZ;
    // A: 128 rows x 96 k fp16 = 192B/row = 12 x 16B chunks -> 1536 tasks
    for (int idx = tid; idx < 1536; idx += NTHR) {
        int r = idx / 12, c = idx - (idx / 12) * 12;
        int gr = row0 + r;
        uint32_t sz = (gr < N_PTS) ? 16u : 0u;
        cp16p(base + (uint32_t)(r * RSTRIDE + c * 16),
              Ahp + (size_t)gr * KDIM + k0 + c * 8, sz);
    }
    // B: 96 rows x 96 k -> 1152 tasks
    for (int idx = tid; idx < 1152; idx += NTHR) {
        int r = idx / 12, c = idx - (idx / 12) * 12;
        size_t go = (size_t)(col0 + r) * KDIM + k0 + c * 8;
        cp16(base + ABYTES + (uint32_t)(r * RSTRIDE + c * 16), Bhp + go);
    }
}

template <int STAGE>
__global__ __launch_bounds__(NTHR, 2)
void mma_gemm_kernel() {
    constexpr int KDIM = (STAGE == 1) ? CDIM : HDIM;
    constexpr int NCH  = KDIM / 96;              // 1 or 3
    const __half* __restrict__ Ahp = (STAGE == 1) ? g_Xh : g_hh;
    const __half* __restrict__ Bhp = (STAGE == 1) ? g_B1h : g_B2h;
    __half* __restrict__ C = (STAGE == 1) ? g_Z : g_Zh;

    extern __shared__ char smem[];
    const uint32_t sb = smem_u32(smem);

    const int tid  = threadIdx.x;
    const int wid  = tid >> 5;
    const int lane = tid & 31;
    const int g    = lane >> 2;        // 0..7
    const int tg   = lane & 3;         // 0..3
    const int wm   = wid & 3;          // M warp 0..3
    const int wn   = wid >> 2;         // N warp 0..2
    const int row0 = blockIdx.y * 128; // M tile (slow grid dim)
    const int col0 = blockIdx.x * 96;  // N tile (fast grid dim -> L2 reuse)

    // ldmatrix lane addressing (byte offsets within a buffer)
    const uint32_t a_lrow = (uint32_t)(wm * 32 + (lane & 15));
    const uint32_t a_loff = a_lrow * RSTRIDE + ((lane >> 4) * 16);
    const uint32_t b_lrow = (uint32_t)(wn * 32 + (lane & 7) + (((lane >> 4) & 1) * 8));
    const uint32_t b_loff = b_lrow * RSTRIDE + (((lane >> 3) & 1) * 16);

    float acc[2][4][4];
    #pragma unroll
    for (int mf = 0; mf < 2; mf++)
        #pragma unroll
        for (int nf = 0; nf < 4; nf++)
            #pragma unroll
            for (int i = 0; i < 4; i++) acc[mf][nf][i] = 0.f;

    gemm_stage<KDIM>(tid, row0, col0, 0, 0, Ahp, Bhp, sb);
    CP_COMMIT();

    for (int kc = 0; kc < NCH; kc++) {
        if (kc + 1 < NCH) {
            gemm_stage<KDIM>(tid, row0, col0, (kc + 1) * 96,
                             (kc + 1) & 1, Ahp, Bhp, sb);
            CP_COMMIT();
            asm volatile("cp.async.wait_group 1;" ::: "memory");
        } else {
            asm volatile("cp.async.wait_group 0;" ::: "memory");
        }
        __syncthreads();

        const uint32_t base = sb + (kc & 1) * BUF_SZ;

        #pragma unroll
        for (int ks = 0; ks < 6; ks++) {          // 6 k16 steps per 96-chunk
            const uint32_t kb = ks * 32;          // 16 f16 = 32 bytes
            uint32_t AH[2][4];
            #pragma unroll
            for (int mf = 0; mf < 2; mf++)
                ldm_x4(AH[mf], base + a_loff + mf * (16 * RSTRIDE) + kb);
            #pragma unroll
            for (int pnf = 0; pnf < 2; pnf++) {
                uint32_t bd = base + ABYTES + b_loff + pnf * (16 * RSTRIDE) + kb;
                uint32_t BH4[4];
                ldm_x4(BH4, bd);
                #pragma unroll
                for (int half = 0; half < 2; half++) {
                    const uint32_t* bh = BH4 + half * 2;
                    mma_f16(acc[0][pnf * 2 + half], AH[0], bh);
                    mma_f16(acc[1][pnf * 2 + half], AH[1], bh);
                }
            }
        }
        __syncthreads();
    }

    // epilogue: fp32 accumulators -> fp16 C
    #pragma unroll
    for (int mf = 0; mf < 2; mf++) {
        int row = row0 + wm * 32 + mf * 16 + g;
        #pragma unroll
        for (int nf = 0; nf < 4; nf++) {
            int col = col0 + wn * 32 + nf * 8 + 2 * tg;
            if (row < N_PTS) {
                __half2 v = __floats2half2_rn(acc[mf][nf][0], acc[mf][nf][1]);
                *(uint32_t*)(C + (size_t)row * HDIM + col) = *(uint32_t*)&v;
            }
            if (row + 8 < N_PTS) {
                __half2 v = __floats2half2_rn(acc[mf][nf][2], acc[mf][nf][3]);
                *(uint32_t*)(C + (size_t)(row + 8) * HDIM + col) = *(uint32_t*)&v;
            }
        }
    }
}

// -------- assemble stage 1:  h = relu(b1 + 3 gathered taps) -> fp16 --------
__global__ __launch_bounds__(256)
void assemble1_kernel(const float* __restrict__ b1) {
    int idx = blockIdx.x * 256 + threadIdx.x;      // N_PTS * 72 tasks (4 elems)
    if (idx >= N_PTS * 72) return;
    int p = idx / 72;
    int gidx = idx - p * 72;
    int c = gidx / 24;          // tap 0..2
    int j = gidx - c * 24;      // 4-elem group within 96
    int prev = g_prev[c * N_PTS + p];
    int next = g_next[c * N_PTS + p];
    float4 v = ((const float4*)b1)[j];
    if (prev >= 0) {
        uint2 z = *(const uint2*)(g_Z + (size_t)prev * HDIM + j * 4);
        float2 z0 = up2(z.x), z1 = up2(z.y);
        v.x += z0.x; v.y += z0.y; v.z += z1.x; v.w += z1.y;
    }
    {
        uint2 z = *(const uint2*)(g_Z + (size_t)p * HDIM + FDIM + j * 4);
        float2 z0 = up2(z.x), z1 = up2(z.y);
        v.x += z0.x; v.y += z0.y; v.z += z1.x; v.w += z1.y;
    }
    if (next >= 0) {
        uint2 z = *(const uint2*)(g_Z + (size_t)next * HDIM + 2 * FDIM + j * 4);
        float2 z0 = up2(z.x), z1 = up2(z.y);
        v.x += z0.x; v.y += z0.y; v.z += z1.x; v.w += z1.y;
    }
    __half2 h0 = __floats2half2_rn(fmaxf(v.x, 0.f), fmaxf(v.y, 0.f));
    __half2 h1 = __floats2half2_rn(fmaxf(v.z, 0.f), fmaxf(v.w, 0.f));
    int o = p * 72 + c * 24 + j;                   // uint2 (4-elem) index
    ((uint2*)g_hh)[o] = make_uint2(*(uint32_t*)&h0, *(uint32_t*)&h1);
}

// ------- assemble stage 2 + residual + layernorm (warp per point) ----------
__global__ __launch_bounds__(256)
void assemble2_ln_kernel(const float* __restrict__ b2,
                         const float* __restrict__ gamma,
                         const float* __restrict__ beta,
                         float* __restrict__ out) {
    int p    = (blockIdx.x * 256 + threadIdx.x) >> 5;   // warp per point
    int lane = threadIdx.x & 31;
    float4 xv[3];
    float s = 0.f, q = 0.f;
    if (lane < 24) {
        #pragma unroll
        for (int c = 0; c < 3; c++) {
            int prev = g_prev[c * N_PTS + p];
            int next = g_next[c * N_PTS + p];
            float4 v = ((const float4*)b2)[lane];
            if (prev >= 0) {
                uint2 z = *(const uint2*)(g_Zh + (size_t)prev * HDIM + lane * 4);
                float2 z0 = up2(z.x), z1 = up2(z.y);
                v.x += z0.x; v.y += z0.y; v.z += z1.x; v.w += z1.y;
            }
            {
                uint2 z = *(const uint2*)(g_Zh + (size_t)p * HDIM + FDIM + lane * 4);
                float2 z0 = up2(z.x), z1 = up2(z.y);
                v.x += z0.x; v.y += z0.y; v.z += z1.x; v.w += z1.y;
            }
            if (next >= 0) {
                uint2 z = *(const uint2*)(g_Zh + (size_t)next * HDIM + 2 * FDIM + lane * 4);
                float2 z0 = up2(z.x), z1 = up2(z.y);
                v.x += z0.x; v.y += z0.y; v.z += z1.x; v.w += z1.y;
            }
            int o = p * 72 + c * 24 + lane;
            uint2 hh = ((const uint2*)g_hh)[o];
            float2 a0 = up2(hh.x), a1 = up2(hh.y);
            float4 x;
            x.x = a0.x + fmaxf(v.x, 0.f);
            x.y = a0.y + fmaxf(v.y, 0.f);
            x.z = a1.x + fmaxf(v.z, 0.f);
            x.w = a1.y + fmaxf(v.w, 0.f);
            xv[c] = x;
            s += x.x + x.y + x.z + x.w;
            q += x.x * x.x + x.y * x.y + x.z * x.z + x.w * x.w;
        }
    }
    #pragma unroll
    for (int o = 16; o > 0; o >>= 1) {
        s += __shfl_xor_sync(0xffffffffu, s, o);
        q += __shfl_xor_sync(0xffffffffu, q, o);
    }
    float mu  = s * (1.f / HDIM);
    float var = q * (1.f / HDIM) - mu * mu;
    float r   = rsqrtf(var + EPSV);
    if (lane < 24) {
        #pragma unroll
        for (int c = 0; c < 3; c++) {
            float4 gm = ((const float4*)gamma)[c * 24 + lane];
            float4 bt = ((const float4*)beta)[c * 24 + lane];
            float4 x  = xv[c];
            float4 o4;
            o4.x = (x.x - mu) * r * gm.x + bt.x;
            o4.y = (x.y - mu) * r * gm.y + bt.y;
            o4.z = (x.z - mu) * r * gm.z + bt.z;
            o4.w = (x.w - mu) * r * gm.w + bt.w;
            *(float4*)(out + (size_t)p * HDIM + c * FDIM + lane * 4) = o4;
        }
    }
}

// ---------------- index pass-through tail ----------------------------------
__global__ void copy_index_kernel(const int* __restrict__ index,
                                  float* __restrict__ out, int count) {
    int t = blockIdx.x * blockDim.x + threadIdx.x;
    if (t < count) out[t] = (float)index[t];
}

// ---------------------------------------------------------------------------
extern "C" void kernel_launch(void* const* d_in, const int* in_sizes, int n_in,
                              void* d_out, int out_size) {
    const float* X     = (const float*)d_in[0];
    const int*   index = (const int*)  d_in[1];
    const float* W1    = (const float*)d_in[2];
    const float* b1    = (const float*)d_in[3];
    const float* W2    = (const float*)d_in[4];
    const float* b2    = (const float*)d_in[5];
    const float* gamma = (const float*)d_in[6];
    const float* beta  = (const float*)d_in[7];
    float* out = (float*)d_out;

    cudaFuncSetAttribute(mma_gemm_kernel<1>,
                         cudaFuncAttributeMaxDynamicSharedMemorySize, GSM_TOTAL);
    cudaFuncSetAttribute(mma_gemm_kernel<2>,
                         cudaFuncAttributeMaxDynamicSharedMemorySize, GSM_TOTAL);

    split_x_kernel<<<(N_PTS * 24 + 255) / 256, 256>>>(X);
    pack_w_kernel<<<(HDIM * HDIM + 255) / 256, 256>>>(W1, W2);
    prevnext_kernel<<<(NCOLS * N_PTS + 255) / 256, 256>>>(index);

    dim3 gg(3, N_MTILE);                          // N fastest -> A L2 reuse
    mma_gemm_kernel<1><<<gg, NTHR, GSM_TOTAL>>>();        // Z  = Xh @ B1h^T
    assemble1_kernel<<<(N_PTS * 72 + 255) / 256, 256>>>(b1);
    mma_gemm_kernel<2><<<gg, NTHR, GSM_TOTAL>>>();        // Zh = hh @ B2h^T
    assemble2_ln_kernel<<<(N_PTS * 32 + 255) / 256, 256>>>(b2, gamma, beta, out);

    int tail = out_size - N_PTS * HDIM;
    if (tail > 0) {
        if (tail > NCOLS * N_PTS) tail = NCOLS * N_PTS;
        copy_index_kernel<<<(tail + 255) / 256, 256>>>(
            index, out + (size_t)N_PTS * HDIM, tail);
    }
}